// round 4
// baseline (speedup 1.0000x reference)
#include <cuda_runtime.h>
#include <math.h>

#define BB 1024
#define TT 512
#define II 4
#define HH 32
#define GG 96   // 3*H

// Scratch sequence buffers (allocation-free rule: __device__ globals).
__device__ float g_h1 [(size_t)BB * TT * 2 * HH];  // layer0 output, concat [fwd|bwd]
__device__ float g_out[(size_t)BB * TT * 2 * HH];  // layer1 output, concat [fwd|bwd]

__device__ __forceinline__ float fsigmoid(float x) {
    return 1.0f / (1.0f + __expf(-x));
}

// ---------------------------------------------------------------------------
// Layer 0: input I=4. One warp per (batch, dir). Lane j owns hidden dim j.
// grid: (B/8, 2), block: 256 (8 warps)
// ---------------------------------------------------------------------------
__global__ void __launch_bounds__(256) gru_l0_kernel(
    const float* __restrict__ x,      // [B,T,4]
    const float* __restrict__ w_ih,   // [2,96,4]
    const float* __restrict__ w_hh,   // [2,96,32]
    const float* __restrict__ b_ih,   // [2,96]
    const float* __restrict__ b_hh)   // [2,96]
{
    __shared__ float sWhh[HH][GG];   // transposed: sWhh[k][g]
    __shared__ float sB[2 * GG];

    const int dir = blockIdx.y;
    const int tid = threadIdx.x;

    const float* whh = w_hh + dir * GG * HH;
    for (int idx = tid; idx < GG * HH; idx += 256) {
        int g = idx / HH, k = idx % HH;
        sWhh[k][g] = whh[idx];
    }
    for (int idx = tid; idx < GG; idx += 256) {
        sB[idx]      = b_ih[dir * GG + idx];
        sB[GG + idx] = b_hh[dir * GG + idx];
    }
    __syncthreads();

    const int warp = tid >> 5;
    const int j    = tid & 31;
    const int b    = blockIdx.x * 8 + warp;

    // per-thread input-projection weights (12 regs)
    const float* wih = w_ih + dir * GG * II;
    float wr0 = wih[(j     ) * 4 + 0], wr1 = wih[(j     ) * 4 + 1],
          wr2 = wih[(j     ) * 4 + 2], wr3 = wih[(j     ) * 4 + 3];
    float wz0 = wih[(j + 32) * 4 + 0], wz1 = wih[(j + 32) * 4 + 1],
          wz2 = wih[(j + 32) * 4 + 2], wz3 = wih[(j + 32) * 4 + 3];
    float wn0 = wih[(j + 64) * 4 + 0], wn1 = wih[(j + 64) * 4 + 1],
          wn2 = wih[(j + 64) * 4 + 2], wn3 = wih[(j + 64) * 4 + 3];

    const float br  = sB[j]      + sB[GG + j];
    const float bz  = sB[32 + j] + sB[GG + 32 + j];
    const float bxn = sB[64 + j];
    const float bhn = sB[GG + 64 + j];

    float h = 0.0f;
    const int tstart = dir ? (TT - 1) : 0;
    const int tstep  = dir ? -1 : 1;

    const float* xb = x + (size_t)b * TT * II;
    float* ob = g_h1 + (size_t)b * TT * 2 * HH + dir * HH + j;

    int t = tstart;
    for (int s = 0; s < TT; ++s, t += tstep) {
        float4 xx = __ldg(reinterpret_cast<const float4*>(xb + (size_t)t * 4));

        float r  = br  + wr0 * xx.x + wr1 * xx.y + wr2 * xx.z + wr3 * xx.w;
        float z  = bz  + wz0 * xx.x + wz1 * xx.y + wz2 * xx.z + wz3 * xx.w;
        float xn = bxn + wn0 * xx.x + wn1 * xx.y + wn2 * xx.z + wn3 * xx.w;
        float hn = bhn;

        #pragma unroll
        for (int k = 0; k < HH; k++) {
            float hk = __shfl_sync(0xffffffffu, h, k);
            r  += sWhh[k][j]      * hk;
            z  += sWhh[k][j + 32] * hk;
            hn += sWhh[k][j + 64] * hk;
        }

        r = fsigmoid(r);
        z = fsigmoid(z);
        float n = tanhf(xn + r * hn);
        h = n + z * (h - n);

        ob[(size_t)t * 2 * HH] = h;
    }
}

// ---------------------------------------------------------------------------
// Layer 1: input = g_h1 (K=64). Input projection fused into the recurrence.
// grid: (B/8, 2), block: 256
// ---------------------------------------------------------------------------
__global__ void __launch_bounds__(256) gru_l1_kernel(
    const float* __restrict__ w_ih,   // [2,96,64]
    const float* __restrict__ w_hh,   // [2,96,32]
    const float* __restrict__ b_ih,   // [2,96]
    const float* __restrict__ b_hh)   // [2,96]
{
    __shared__ float sWih[2 * HH][GG];  // transposed: sWih[k][g], k in [0,64)
    __shared__ float sWhh[HH][GG];
    __shared__ float sB[2 * GG];

    const int dir = blockIdx.y;
    const int tid = threadIdx.x;

    const float* wih = w_ih + dir * GG * 2 * HH;
    for (int idx = tid; idx < GG * 2 * HH; idx += 256) {
        int g = idx / (2 * HH), k = idx % (2 * HH);
        sWih[k][g] = wih[idx];
    }
    const float* whh = w_hh + dir * GG * HH;
    for (int idx = tid; idx < GG * HH; idx += 256) {
        int g = idx / HH, k = idx % HH;
        sWhh[k][g] = whh[idx];
    }
    for (int idx = tid; idx < GG; idx += 256) {
        sB[idx]      = b_ih[dir * GG + idx];
        sB[GG + idx] = b_hh[dir * GG + idx];
    }
    __syncthreads();

    const int warp = tid >> 5;
    const int j    = tid & 31;
    const int b    = blockIdx.x * 8 + warp;

    const float br  = sB[j]      + sB[GG + j];
    const float bz  = sB[32 + j] + sB[GG + 32 + j];
    const float bxn = sB[64 + j];
    const float bhn = sB[GG + 64 + j];

    float h = 0.0f;
    const int tstart = dir ? (TT - 1) : 0;
    const int tstep  = dir ? -1 : 1;

    const float* ib = g_h1 + (size_t)b * TT * 2 * HH;
    float* ob = g_out + (size_t)b * TT * 2 * HH + dir * HH + j;

    int t = tstart;
    for (int s = 0; s < TT; ++s, t += tstep) {
        const float* ip = ib + (size_t)t * 2 * HH;
        float a = ip[j];
        float c = ip[j + 32];

        float r  = br;
        float z  = bz;
        float xn = bxn;
        float hn = bhn;

        #pragma unroll
        for (int k = 0; k < 32; k++) {
            float xk = __shfl_sync(0xffffffffu, a, k);
            r  += sWih[k][j]      * xk;
            z  += sWih[k][j + 32] * xk;
            xn += sWih[k][j + 64] * xk;
        }
        #pragma unroll
        for (int k = 0; k < 32; k++) {
            float xk = __shfl_sync(0xffffffffu, c, k);
            r  += sWih[32 + k][j]      * xk;
            z  += sWih[32 + k][j + 32] * xk;
            xn += sWih[32 + k][j + 64] * xk;
        }
        #pragma unroll
        for (int k = 0; k < HH; k++) {
            float hk = __shfl_sync(0xffffffffu, h, k);
            r  += sWhh[k][j]      * hk;
            z  += sWhh[k][j + 32] * hk;
            hn += sWhh[k][j + 64] * hk;
        }

        r = fsigmoid(r);
        z = fsigmoid(z);
        float n = tanhf(xn + r * hn);
        h = n + z * (h - n);

        ob[(size_t)t * 2 * HH] = h;
    }
}

// ---------------------------------------------------------------------------
// Epilogue: attention-softmax pooling over T + sigmoid FC. One block per batch.
// ---------------------------------------------------------------------------
__global__ void __launch_bounds__(256) attn_fc_kernel(
    const float* __restrict__ attn_w,  // [1,64]
    const float* __restrict__ fc_w,    // [1,64]
    const float* __restrict__ fc_b,    // [1]
    float* __restrict__ y)             // [B,1]
{
    __shared__ float sl[TT];
    __shared__ float saw[64], sfw[64];
    __shared__ float redm[8], reds[8];
    __shared__ float sctx[64];

    const int b    = blockIdx.x;
    const int tid  = threadIdx.x;
    const int warp = tid >> 5;
    const int lane = tid & 31;

    if (tid < 64) {
        saw[tid]  = attn_w[tid];
        sfw[tid]  = fc_w[tid];
        sctx[tid] = 0.0f;
    }
    __syncthreads();

    const float* ob = g_out + (size_t)b * TT * 64;

    // logits (attn_b constant over T -> cancels in softmax)
    for (int t = warp; t < TT; t += 8) {
        const float* p = ob + (size_t)t * 64;
        float v = p[lane] * saw[lane] + p[lane + 32] * saw[lane + 32];
        #pragma unroll
        for (int o = 16; o; o >>= 1) v += __shfl_xor_sync(0xffffffffu, v, o);
        if (lane == 0) sl[t] = v;
    }
    __syncthreads();

    // max
    float m = -INFINITY;
    for (int t = tid; t < TT; t += 256) m = fmaxf(m, sl[t]);
    #pragma unroll
    for (int o = 16; o; o >>= 1) m = fmaxf(m, __shfl_xor_sync(0xffffffffu, m, o));
    if (lane == 0) redm[warp] = m;
    __syncthreads();
    float mm = redm[0];
    #pragma unroll
    for (int w = 1; w < 8; w++) mm = fmaxf(mm, redm[w]);

    // exp + sum
    float ssum = 0.0f;
    for (int t = tid; t < TT; t += 256) {
        float p = __expf(sl[t] - mm);
        sl[t] = p;
        ssum += p;
    }
    #pragma unroll
    for (int o = 16; o; o >>= 1) ssum += __shfl_xor_sync(0xffffffffu, ssum, o);
    if (lane == 0) reds[warp] = ssum;
    __syncthreads();

    // ctx accumulation (unnormalized)
    float c0 = 0.0f, c1 = 0.0f;
    for (int t = warp; t < TT; t += 8) {
        float p = sl[t];
        const float* q = ob + (size_t)t * 64;
        c0 += p * q[lane];
        c1 += p * q[lane + 32];
    }
    atomicAdd(&sctx[lane], c0);
    atomicAdd(&sctx[lane + 32], c1);
    __syncthreads();

    if (tid < 32) {
        float Z = reds[0];
        #pragma unroll
        for (int w = 1; w < 8; w++) Z += reds[w];
        float v = sctx[lane] * sfw[lane] + sctx[lane + 32] * sfw[lane + 32];
        #pragma unroll
        for (int o = 16; o; o >>= 1) v += __shfl_xor_sync(0xffffffffu, v, o);
        if (lane == 0) {
            y[b] = 1.0f / (1.0f + __expf(-(v / Z + fc_b[0])));
        }
    }
}

extern "C" void kernel_launch(void* const* d_in, const int* in_sizes, int n_in,
                              void* d_out, int out_size) {
    const float* x       = (const float*)d_in[0];
    const float* w_ih_l0 = (const float*)d_in[1];
    const float* w_hh_l0 = (const float*)d_in[2];
    const float* b_ih_l0 = (const float*)d_in[3];
    const float* b_hh_l0 = (const float*)d_in[4];
    const float* w_ih_l1 = (const float*)d_in[5];
    const float* w_hh_l1 = (const float*)d_in[6];
    const float* b_ih_l1 = (const float*)d_in[7];
    const float* b_hh_l1 = (const float*)d_in[8];
    const float* attn_w  = (const float*)d_in[9];
    // d_in[10] = attn_b (cancels in softmax)
    const float* fc_w    = (const float*)d_in[11];
    const float* fc_b    = (const float*)d_in[12];
    float* y = (float*)d_out;

    dim3 grid(BB / 8, 2);
    gru_l0_kernel<<<grid, 256>>>(x, w_ih_l0, w_hh_l0, b_ih_l0, b_hh_l0);
    gru_l1_kernel<<<grid, 256>>>(w_ih_l1, w_hh_l1, b_ih_l1, b_hh_l1);
    attn_fc_kernel<<<BB, 256>>>(attn_w, fc_w, fc_b, y);
}

// round 5
// speedup vs baseline: 1.0003x; 1.0003x over previous
#include <cuda_runtime.h>
#include <math.h>

#define BB 1024
#define TT 512
#define II 4
#define HH 32
#define GG 96   // 3*H

// Scratch sequence buffers (allocation-free rule: __device__ globals).
__device__ float g_h1 [(size_t)BB * TT * 2 * HH];  // layer0 output, concat [fwd|bwd]
__device__ float g_out[(size_t)BB * TT * 2 * HH];  // layer1 output, concat [fwd|bwd]

__device__ __forceinline__ float fsigmoid(float x) {
    return 1.0f / (1.0f + __expf(-x));
}

// ---------------------------------------------------------------------------
// Layer 0: input I=4. One warp per (batch, dir). Lane j owns hidden dim j.
// grid: (B/8, 2), block: 256 (8 warps)
// ---------------------------------------------------------------------------
__global__ void __launch_bounds__(256) gru_l0_kernel(
    const float* __restrict__ x,      // [B,T,4]
    const float* __restrict__ w_ih,   // [2,96,4]
    const float* __restrict__ w_hh,   // [2,96,32]
    const float* __restrict__ b_ih,   // [2,96]
    const float* __restrict__ b_hh)   // [2,96]
{
    __shared__ float sWhh[HH][GG];   // transposed: sWhh[k][g]
    __shared__ float sB[2 * GG];

    const int dir = blockIdx.y;
    const int tid = threadIdx.x;

    const float* whh = w_hh + dir * GG * HH;
    for (int idx = tid; idx < GG * HH; idx += 256) {
        int g = idx / HH, k = idx % HH;
        sWhh[k][g] = whh[idx];
    }
    for (int idx = tid; idx < GG; idx += 256) {
        sB[idx]      = b_ih[dir * GG + idx];
        sB[GG + idx] = b_hh[dir * GG + idx];
    }
    __syncthreads();

    const int warp = tid >> 5;
    const int j    = tid & 31;
    const int b    = blockIdx.x * 8 + warp;

    // per-thread input-projection weights (12 regs)
    const float* wih = w_ih + dir * GG * II;
    float wr0 = wih[(j     ) * 4 + 0], wr1 = wih[(j     ) * 4 + 1],
          wr2 = wih[(j     ) * 4 + 2], wr3 = wih[(j     ) * 4 + 3];
    float wz0 = wih[(j + 32) * 4 + 0], wz1 = wih[(j + 32) * 4 + 1],
          wz2 = wih[(j + 32) * 4 + 2], wz3 = wih[(j + 32) * 4 + 3];
    float wn0 = wih[(j + 64) * 4 + 0], wn1 = wih[(j + 64) * 4 + 1],
          wn2 = wih[(j + 64) * 4 + 2], wn3 = wih[(j + 64) * 4 + 3];

    const float br  = sB[j]      + sB[GG + j];
    const float bz  = sB[32 + j] + sB[GG + 32 + j];
    const float bxn = sB[64 + j];
    const float bhn = sB[GG + 64 + j];

    float h = 0.0f;
    const int tstart = dir ? (TT - 1) : 0;
    const int tstep  = dir ? -1 : 1;

    const float* xb = x + (size_t)b * TT * II;
    float* ob = g_h1 + (size_t)b * TT * 2 * HH + dir * HH + j;

    int t = tstart;
    for (int s = 0; s < TT; ++s, t += tstep) {
        float4 xx = __ldg(reinterpret_cast<const float4*>(xb + (size_t)t * 4));

        float r  = br  + wr0 * xx.x + wr1 * xx.y + wr2 * xx.z + wr3 * xx.w;
        float z  = bz  + wz0 * xx.x + wz1 * xx.y + wz2 * xx.z + wz3 * xx.w;
        float xn = bxn + wn0 * xx.x + wn1 * xx.y + wn2 * xx.z + wn3 * xx.w;
        float hn = bhn;

        #pragma unroll
        for (int k = 0; k < HH; k++) {
            float hk = __shfl_sync(0xffffffffu, h, k);
            r  += sWhh[k][j]      * hk;
            z  += sWhh[k][j + 32] * hk;
            hn += sWhh[k][j + 64] * hk;
        }

        r = fsigmoid(r);
        z = fsigmoid(z);
        float n = tanhf(xn + r * hn);
        h = n + z * (h - n);

        ob[(size_t)t * 2 * HH] = h;
    }
}

// ---------------------------------------------------------------------------
// Layer 1: input = g_h1 (K=64). Input projection fused into the recurrence.
// grid: (B/8, 2), block: 256
// ---------------------------------------------------------------------------
__global__ void __launch_bounds__(256) gru_l1_kernel(
    const float* __restrict__ w_ih,   // [2,96,64]
    const float* __restrict__ w_hh,   // [2,96,32]
    const float* __restrict__ b_ih,   // [2,96]
    const float* __restrict__ b_hh)   // [2,96]
{
    __shared__ float sWih[2 * HH][GG];  // transposed: sWih[k][g], k in [0,64)
    __shared__ float sWhh[HH][GG];
    __shared__ float sB[2 * GG];

    const int dir = blockIdx.y;
    const int tid = threadIdx.x;

    const float* wih = w_ih + dir * GG * 2 * HH;
    for (int idx = tid; idx < GG * 2 * HH; idx += 256) {
        int g = idx / (2 * HH), k = idx % (2 * HH);
        sWih[k][g] = wih[idx];
    }
    const float* whh = w_hh + dir * GG * HH;
    for (int idx = tid; idx < GG * HH; idx += 256) {
        int g = idx / HH, k = idx % HH;
        sWhh[k][g] = whh[idx];
    }
    for (int idx = tid; idx < GG; idx += 256) {
        sB[idx]      = b_ih[dir * GG + idx];
        sB[GG + idx] = b_hh[dir * GG + idx];
    }
    __syncthreads();

    const int warp = tid >> 5;
    const int j    = tid & 31;
    const int b    = blockIdx.x * 8 + warp;

    const float br  = sB[j]      + sB[GG + j];
    const float bz  = sB[32 + j] + sB[GG + 32 + j];
    const float bxn = sB[64 + j];
    const float bhn = sB[GG + 64 + j];

    float h = 0.0f;
    const int tstart = dir ? (TT - 1) : 0;
    const int tstep  = dir ? -1 : 1;

    const float* ib = g_h1 + (size_t)b * TT * 2 * HH;
    float* ob = g_out + (size_t)b * TT * 2 * HH + dir * HH + j;

    int t = tstart;
    for (int s = 0; s < TT; ++s, t += tstep) {
        const float* ip = ib + (size_t)t * 2 * HH;
        float a = ip[j];
        float c = ip[j + 32];

        float r  = br;
        float z  = bz;
        float xn = bxn;
        float hn = bhn;

        #pragma unroll
        for (int k = 0; k < 32; k++) {
            float xk = __shfl_sync(0xffffffffu, a, k);
            r  += sWih[k][j]      * xk;
            z  += sWih[k][j + 32] * xk;
            xn += sWih[k][j + 64] * xk;
        }
        #pragma unroll
        for (int k = 0; k < 32; k++) {
            float xk = __shfl_sync(0xffffffffu, c, k);
            r  += sWih[32 + k][j]      * xk;
            z  += sWih[32 + k][j + 32] * xk;
            xn += sWih[32 + k][j + 64] * xk;
        }
        #pragma unroll
        for (int k = 0; k < HH; k++) {
            float hk = __shfl_sync(0xffffffffu, h, k);
            r  += sWhh[k][j]      * hk;
            z  += sWhh[k][j + 32] * hk;
            hn += sWhh[k][j + 64] * hk;
        }

        r = fsigmoid(r);
        z = fsigmoid(z);
        float n = tanhf(xn + r * hn);
        h = n + z * (h - n);

        ob[(size_t)t * 2 * HH] = h;
    }
}

// ---------------------------------------------------------------------------
// Epilogue: attention-softmax pooling over T + sigmoid FC. One block per batch.
// ---------------------------------------------------------------------------
__global__ void __launch_bounds__(256) attn_fc_kernel(
    const float* __restrict__ attn_w,  // [1,64]
    const float* __restrict__ fc_w,    // [1,64]
    const float* __restrict__ fc_b,    // [1]
    float* __restrict__ y)             // [B,1]
{
    __shared__ float sl[TT];
    __shared__ float saw[64], sfw[64];
    __shared__ float redm[8], reds[8];
    __shared__ float sctx[64];

    const int b    = blockIdx.x;
    const int tid  = threadIdx.x;
    const int warp = tid >> 5;
    const int lane = tid & 31;

    if (tid < 64) {
        saw[tid]  = attn_w[tid];
        sfw[tid]  = fc_w[tid];
        sctx[tid] = 0.0f;
    }
    __syncthreads();

    const float* ob = g_out + (size_t)b * TT * 64;

    // logits (attn_b constant over T -> cancels in softmax)
    for (int t = warp; t < TT; t += 8) {
        const float* p = ob + (size_t)t * 64;
        float v = p[lane] * saw[lane] + p[lane + 32] * saw[lane + 32];
        #pragma unroll
        for (int o = 16; o; o >>= 1) v += __shfl_xor_sync(0xffffffffu, v, o);
        if (lane == 0) sl[t] = v;
    }
    __syncthreads();

    // max
    float m = -INFINITY;
    for (int t = tid; t < TT; t += 256) m = fmaxf(m, sl[t]);
    #pragma unroll
    for (int o = 16; o; o >>= 1) m = fmaxf(m, __shfl_xor_sync(0xffffffffu, m, o));
    if (lane == 0) redm[warp] = m;
    __syncthreads();
    float mm = redm[0];
    #pragma unroll
    for (int w = 1; w < 8; w++) mm = fmaxf(mm, redm[w]);

    // exp + sum
    float ssum = 0.0f;
    for (int t = tid; t < TT; t += 256) {
        float p = __expf(sl[t] - mm);
        sl[t] = p;
        ssum += p;
    }
    #pragma unroll
    for (int o = 16; o; o >>= 1) ssum += __shfl_xor_sync(0xffffffffu, ssum, o);
    if (lane == 0) reds[warp] = ssum;
    __syncthreads();

    // ctx accumulation (unnormalized)
    float c0 = 0.0f, c1 = 0.0f;
    for (int t = warp; t < TT; t += 8) {
        float p = sl[t];
        const float* q = ob + (size_t)t * 64;
        c0 += p * q[lane];
        c1 += p * q[lane + 32];
    }
    atomicAdd(&sctx[lane], c0);
    atomicAdd(&sctx[lane + 32], c1);
    __syncthreads();

    if (tid < 32) {
        float Z = reds[0];
        #pragma unroll
        for (int w = 1; w < 8; w++) Z += reds[w];
        float v = sctx[lane] * sfw[lane] + sctx[lane + 32] * sfw[lane + 32];
        #pragma unroll
        for (int o = 16; o; o >>= 1) v += __shfl_xor_sync(0xffffffffu, v, o);
        if (lane == 0) {
            y[b] = 1.0f / (1.0f + __expf(-(v / Z + fc_b[0])));
        }
    }
}

extern "C" void kernel_launch(void* const* d_in, const int* in_sizes, int n_in,
                              void* d_out, int out_size) {
    const float* x       = (const float*)d_in[0];
    const float* w_ih_l0 = (const float*)d_in[1];
    const float* w_hh_l0 = (const float*)d_in[2];
    const float* b_ih_l0 = (const float*)d_in[3];
    const float* b_hh_l0 = (const float*)d_in[4];
    const float* w_ih_l1 = (const float*)d_in[5];
    const float* w_hh_l1 = (const float*)d_in[6];
    const float* b_ih_l1 = (const float*)d_in[7];
    const float* b_hh_l1 = (const float*)d_in[8];
    const float* attn_w  = (const float*)d_in[9];
    // d_in[10] = attn_b (cancels in softmax)
    const float* fc_w    = (const float*)d_in[11];
    const float* fc_b    = (const float*)d_in[12];
    float* y = (float*)d_out;

    dim3 grid(BB / 8, 2);
    gru_l0_kernel<<<grid, 256>>>(x, w_ih_l0, w_hh_l0, b_ih_l0, b_hh_l0);
    gru_l1_kernel<<<grid, 256>>>(w_ih_l1, w_hh_l1, b_ih_l1, b_hh_l1);
    attn_fc_kernel<<<BB, 256>>>(attn_w, fc_w, fc_b, y);
}

// round 6
// speedup vs baseline: 1.4976x; 1.4972x over previous
#include <cuda_runtime.h>
#include <math.h>

#define BB 1024
#define TT 512
#define II 4
#define HH 32
#define GG 96   // 3*H

typedef unsigned long long u64;

// Scratch sequence buffers (allocation-free rule: __device__ globals).
__device__ float g_h1 [(size_t)BB * TT * 2 * HH];        // layer0 out [b][t][dir*32+j]
__device__ float g_xg [(size_t)2 * BB * TT * GG];        // layer1 input proj [dir][b][t][96]
__device__ float g_out[(size_t)BB * TT * 2 * HH];        // layer1 out

__device__ __forceinline__ u64 fma2(u64 a, u64 b, u64 c) {
    u64 d;
    asm("fma.rn.f32x2 %0, %1, %2, %3;" : "=l"(d) : "l"(a), "l"(b), "l"(c));
    return d;
}
__device__ __forceinline__ float sum2(u64 v) {
    float lo, hi;
    asm("mov.b64 {%0, %1}, %2;" : "=f"(lo), "=f"(hi) : "l"(v));
    return lo + hi;
}
__device__ __forceinline__ float fsig(float x) {
    return 1.0f / (1.0f + __expf(-x));
}
__device__ __forceinline__ float ftanh(float x) {
    return 2.0f / (1.0f + __expf(-2.0f * x)) - 1.0f;
}

// ---------------------------------------------------------------------------
// Layer 0: one warp per (b, dir). Lane j owns hidden dim j.
// W_hh in registers (48 packed u64), h broadcast via double-buffered smem.
// grid: (B/2, 2), block 64 (2 warps).
// ---------------------------------------------------------------------------
__global__ void __launch_bounds__(64, 7) gru_l0_reg(
    const float* __restrict__ x,      // [B,T,4]
    const float* __restrict__ w_ih,   // [2,96,4]
    const float* __restrict__ w_hh,   // [2,96,32]
    const float* __restrict__ b_ih,   // [2,96]
    const float* __restrict__ b_hh)   // [2,96]
{
    __shared__ float sh[2][2][32];    // [warp][parity][lane]

    const int warp = threadIdx.x >> 5;
    const int j    = threadIdx.x & 31;
    const int dir  = blockIdx.y;
    const int b    = blockIdx.x * 2 + warp;

    // recurrent weights: lane j needs row j (r), 32+j (z), 64+j (n); packed pairs
    const u64* w64 = (const u64*)w_hh;     // each 32-float row = 16 u64
    u64 wr2[16], wz2[16], wn2[16];
    {
        const int rb = (dir * GG + j) * 16;
        const int zb = (dir * GG + 32 + j) * 16;
        const int nb = (dir * GG + 64 + j) * 16;
        #pragma unroll
        for (int m = 0; m < 16; m++) {
            wr2[m] = w64[rb + m];
            wz2[m] = w64[zb + m];
            wn2[m] = w64[nb + m];
        }
    }
    // input-projection weights (I=4) as float4 per gate row
    const float4 wr4 = ((const float4*)w_ih)[dir * GG + j];
    const float4 wz4 = ((const float4*)w_ih)[dir * GG + 32 + j];
    const float4 wn4 = ((const float4*)w_ih)[dir * GG + 64 + j];

    const float br  = b_ih[dir * GG + j]      + b_hh[dir * GG + j];
    const float bz  = b_ih[dir * GG + 32 + j] + b_hh[dir * GG + 32 + j];
    const float bxn = b_ih[dir * GG + 64 + j];
    const float bhn = b_hh[dir * GG + 64 + j];

    float h = 0.0f;
    const int tstep = dir ? -1 : 1;
    int t = dir ? (TT - 1) : 0;

    const float* xb = x + (size_t)b * TT * II;
    float* ob = g_h1 + (size_t)b * TT * 2 * HH + dir * HH + j;

    for (int s = 0; s < TT; ++s, t += tstep) {
        const float4 xx = __ldg(reinterpret_cast<const float4*>(xb + (size_t)t * 4));
        float rin = br  + wr4.x * xx.x + wr4.y * xx.y + wr4.z * xx.z + wr4.w * xx.w;
        float zin = bz  + wz4.x * xx.x + wz4.y * xx.y + wz4.z * xx.z + wz4.w * xx.w;
        float nin = bxn + wn4.x * xx.x + wn4.y * xx.y + wn4.z * xx.z + wn4.w * xx.w;

        const int par = s & 1;
        sh[warp][par][j] = h;
        __syncwarp();

        u64 r2 = 0ULL, z2 = 0ULL, n2 = 0ULL;
        const ulonglong2* hv = (const ulonglong2*)sh[warp][par];
        #pragma unroll
        for (int q = 0; q < 8; q++) {
            const ulonglong2 hp = hv[q];
            r2 = fma2(wr2[2 * q],     hp.x, r2);
            z2 = fma2(wz2[2 * q],     hp.x, z2);
            n2 = fma2(wn2[2 * q],     hp.x, n2);
            r2 = fma2(wr2[2 * q + 1], hp.y, r2);
            z2 = fma2(wz2[2 * q + 1], hp.y, z2);
            n2 = fma2(wn2[2 * q + 1], hp.y, n2);
        }

        const float r = fsig(rin + sum2(r2));
        const float z = fsig(zin + sum2(z2));
        const float n = ftanh(nin + r * (bhn + sum2(n2)));
        h = n + z * (h - n);

        ob[(size_t)t * 2 * HH] = h;
    }
}

// ---------------------------------------------------------------------------
// Layer 1 input projection (GEMM): xg[dir][b][t][96] = h1[b][t] @ W_ih^T + b_ih
// One warp per (b, dir, t-chunk of 128). Weights in registers (96 packed u64).
// grid: (B/2, 4, 2), block 64.
// ---------------------------------------------------------------------------
__global__ void __launch_bounds__(64) gru_l1_xg(
    const float* __restrict__ w_ih,   // [2,96,64]
    const float* __restrict__ b_ih)   // [2,96]
{
    __shared__ float sh[2][2][64];    // [warp][parity][k]

    const int warp = threadIdx.x >> 5;
    const int j    = threadIdx.x & 31;
    const int dir  = blockIdx.z;
    const int b    = blockIdx.x * 2 + warp;
    const int t0   = blockIdx.y * (TT / 4);

    const u64* w64 = (const u64*)w_ih;     // each 64-float row = 32 u64
    u64 wr2[32], wz2[32], wn2[32];
    {
        const int rb = (dir * GG + j) * 32;
        const int zb = (dir * GG + 32 + j) * 32;
        const int nb = (dir * GG + 64 + j) * 32;
        #pragma unroll
        for (int m = 0; m < 32; m++) {
            wr2[m] = w64[rb + m];
            wz2[m] = w64[zb + m];
            wn2[m] = w64[nb + m];
        }
    }
    const float br = b_ih[dir * GG + j];
    const float bz = b_ih[dir * GG + 32 + j];
    const float bn = b_ih[dir * GG + 64 + j];

    const float* ib = g_h1 + (size_t)b * TT * 2 * HH;
    float* xgb = g_xg + (((size_t)dir * BB + b) * TT) * GG;

    for (int t = t0; t < t0 + TT / 4; ++t) {
        const float* ip = ib + (size_t)t * 64;
        const float a = ip[j];
        const float c = ip[j + 32];

        const int par = t & 1;
        sh[warp][par][j]      = a;
        sh[warp][par][j + 32] = c;
        __syncwarp();

        u64 r2 = 0ULL, z2 = 0ULL, n2 = 0ULL;
        const ulonglong2* hv = (const ulonglong2*)sh[warp][par];
        #pragma unroll
        for (int q = 0; q < 16; q++) {
            const ulonglong2 hp = hv[q];
            r2 = fma2(wr2[2 * q],     hp.x, r2);
            z2 = fma2(wz2[2 * q],     hp.x, z2);
            n2 = fma2(wn2[2 * q],     hp.x, n2);
            r2 = fma2(wr2[2 * q + 1], hp.y, r2);
            z2 = fma2(wz2[2 * q + 1], hp.y, z2);
            n2 = fma2(wn2[2 * q + 1], hp.y, n2);
        }

        float* op = xgb + (size_t)t * GG;
        op[j]      = br + sum2(r2);
        op[j + 32] = bz + sum2(z2);
        op[j + 64] = bn + sum2(n2);
    }
}

// ---------------------------------------------------------------------------
// Layer 1 recurrence: reads precomputed xg. Same structure as layer0.
// grid: (B/2, 2), block 64.
// ---------------------------------------------------------------------------
__global__ void __launch_bounds__(64, 7) gru_l1_rec(
    const float* __restrict__ w_hh,   // [2,96,32]
    const float* __restrict__ b_hh)   // [2,96]
{
    __shared__ float sh[2][2][32];

    const int warp = threadIdx.x >> 5;
    const int j    = threadIdx.x & 31;
    const int dir  = blockIdx.y;
    const int b    = blockIdx.x * 2 + warp;

    const u64* w64 = (const u64*)w_hh;
    u64 wr2[16], wz2[16], wn2[16];
    {
        const int rb = (dir * GG + j) * 16;
        const int zb = (dir * GG + 32 + j) * 16;
        const int nb = (dir * GG + 64 + j) * 16;
        #pragma unroll
        for (int m = 0; m < 16; m++) {
            wr2[m] = w64[rb + m];
            wz2[m] = w64[zb + m];
            wn2[m] = w64[nb + m];
        }
    }
    const float brh = b_hh[dir * GG + j];
    const float bzh = b_hh[dir * GG + 32 + j];
    const float bhn = b_hh[dir * GG + 64 + j];

    float h = 0.0f;
    const int tstep = dir ? -1 : 1;
    int t = dir ? (TT - 1) : 0;

    const float* xgb = g_xg + (((size_t)dir * BB + b) * TT) * GG;
    float* ob = g_out + (size_t)b * TT * 2 * HH + dir * HH + j;

    for (int s = 0; s < TT; ++s, t += tstep) {
        const float* gp = xgb + (size_t)t * GG;
        const float rin = gp[j]      + brh;
        const float zin = gp[j + 32] + bzh;
        const float nin = gp[j + 64];

        const int par = s & 1;
        sh[warp][par][j] = h;
        __syncwarp();

        u64 r2 = 0ULL, z2 = 0ULL, n2 = 0ULL;
        const ulonglong2* hv = (const ulonglong2*)sh[warp][par];
        #pragma unroll
        for (int q = 0; q < 8; q++) {
            const ulonglong2 hp = hv[q];
            r2 = fma2(wr2[2 * q],     hp.x, r2);
            z2 = fma2(wz2[2 * q],     hp.x, z2);
            n2 = fma2(wn2[2 * q],     hp.x, n2);
            r2 = fma2(wr2[2 * q + 1], hp.y, r2);
            z2 = fma2(wz2[2 * q + 1], hp.y, z2);
            n2 = fma2(wn2[2 * q + 1], hp.y, n2);
        }

        const float r = fsig(rin + sum2(r2));
        const float z = fsig(zin + sum2(z2));
        const float n = ftanh(nin + r * (bhn + sum2(n2)));
        h = n + z * (h - n);

        ob[(size_t)t * 2 * HH] = h;
    }
}

// ---------------------------------------------------------------------------
// Epilogue: attention-softmax pooling over T + sigmoid FC. One block per batch.
// ---------------------------------------------------------------------------
__global__ void __launch_bounds__(256) attn_fc_kernel(
    const float* __restrict__ attn_w,  // [1,64]
    const float* __restrict__ fc_w,    // [1,64]
    const float* __restrict__ fc_b,    // [1]
    float* __restrict__ y)             // [B,1]
{
    __shared__ float sl[TT];
    __shared__ float saw[64], sfw[64];
    __shared__ float redm[8], reds[8];
    __shared__ float sctx[64];

    const int b    = blockIdx.x;
    const int tid  = threadIdx.x;
    const int warp = tid >> 5;
    const int lane = tid & 31;

    if (tid < 64) {
        saw[tid]  = attn_w[tid];
        sfw[tid]  = fc_w[tid];
        sctx[tid] = 0.0f;
    }
    __syncthreads();

    const float* ob = g_out + (size_t)b * TT * 64;

    // logits (attn_b constant over T -> cancels in softmax)
    for (int t = warp; t < TT; t += 8) {
        const float* p = ob + (size_t)t * 64;
        float v = p[lane] * saw[lane] + p[lane + 32] * saw[lane + 32];
        #pragma unroll
        for (int o = 16; o; o >>= 1) v += __shfl_xor_sync(0xffffffffu, v, o);
        if (lane == 0) sl[t] = v;
    }
    __syncthreads();

    // max
    float m = -INFINITY;
    for (int t = tid; t < TT; t += 256) m = fmaxf(m, sl[t]);
    #pragma unroll
    for (int o = 16; o; o >>= 1) m = fmaxf(m, __shfl_xor_sync(0xffffffffu, m, o));
    if (lane == 0) redm[warp] = m;
    __syncthreads();
    float mm = redm[0];
    #pragma unroll
    for (int w = 1; w < 8; w++) mm = fmaxf(mm, redm[w]);

    // exp + sum
    float ssum = 0.0f;
    for (int t = tid; t < TT; t += 256) {
        float p = __expf(sl[t] - mm);
        sl[t] = p;
        ssum += p;
    }
    #pragma unroll
    for (int o = 16; o; o >>= 1) ssum += __shfl_xor_sync(0xffffffffu, ssum, o);
    if (lane == 0) reds[warp] = ssum;
    __syncthreads();

    // ctx accumulation (unnormalized)
    float c0 = 0.0f, c1 = 0.0f;
    for (int t = warp; t < TT; t += 8) {
        float p = sl[t];
        const float* q = ob + (size_t)t * 64;
        c0 += p * q[lane];
        c1 += p * q[lane + 32];
    }
    atomicAdd(&sctx[lane], c0);
    atomicAdd(&sctx[lane + 32], c1);
    __syncthreads();

    if (tid < 32) {
        float Z = reds[0];
        #pragma unroll
        for (int w = 1; w < 8; w++) Z += reds[w];
        float v = sctx[lane] * sfw[lane] + sctx[lane + 32] * sfw[lane + 32];
        #pragma unroll
        for (int o = 16; o; o >>= 1) v += __shfl_xor_sync(0xffffffffu, v, o);
        if (lane == 0) {
            y[b] = 1.0f / (1.0f + __expf(-(v / Z + fc_b[0])));
        }
    }
}

extern "C" void kernel_launch(void* const* d_in, const int* in_sizes, int n_in,
                              void* d_out, int out_size) {
    const float* x       = (const float*)d_in[0];
    const float* w_ih_l0 = (const float*)d_in[1];
    const float* w_hh_l0 = (const float*)d_in[2];
    const float* b_ih_l0 = (const float*)d_in[3];
    const float* b_hh_l0 = (const float*)d_in[4];
    const float* w_ih_l1 = (const float*)d_in[5];
    const float* w_hh_l1 = (const float*)d_in[6];
    const float* b_ih_l1 = (const float*)d_in[7];
    const float* b_hh_l1 = (const float*)d_in[8];
    const float* attn_w  = (const float*)d_in[9];
    // d_in[10] = attn_b (cancels in softmax)
    const float* fc_w    = (const float*)d_in[11];
    const float* fc_b    = (const float*)d_in[12];
    float* y = (float*)d_out;

    gru_l0_reg<<<dim3(BB / 2, 2), 64>>>(x, w_ih_l0, w_hh_l0, b_ih_l0, b_hh_l0);
    gru_l1_xg <<<dim3(BB / 2, 4, 2), 64>>>(w_ih_l1, b_ih_l1);
    gru_l1_rec<<<dim3(BB / 2, 2), 64>>>(w_hh_l1, b_hh_l1);
    attn_fc_kernel<<<BB, 256>>>(attn_w, fc_w, fc_b, y);
}

// round 7
// speedup vs baseline: 1.9800x; 1.3221x over previous
#include <cuda_runtime.h>
#include <math.h>

#define BB 1024
#define TT 512
#define II 4
#define HH 32
#define GG 96   // 3*H

typedef unsigned long long u64;

// Scratch sequence buffers (allocation-free rule: __device__ globals).
__device__ float g_h1 [(size_t)BB * TT * 2 * HH];   // layer0 out [b][t][dir*32+j]
__device__ float g_xg [(size_t)2 * BB * TT * GG];   // layer1 input proj [dir][b][t][96]
__device__ float g_out[(size_t)BB * TT * 2 * HH];   // layer1 out

__device__ __forceinline__ u64 fma2(u64 a, u64 b, u64 c) {
    u64 d;
    asm("fma.rn.f32x2 %0, %1, %2, %3;" : "=l"(d) : "l"(a), "l"(b), "l"(c));
    return d;
}
__device__ __forceinline__ u64 add2(u64 a, u64 b) {
    u64 d;
    asm("add.rn.f32x2 %0, %1, %2;" : "=l"(d) : "l"(a), "l"(b));
    return d;
}
__device__ __forceinline__ float sum2(u64 v) {
    float lo, hi;
    asm("mov.b64 {%0, %1}, %2;" : "=f"(lo), "=f"(hi) : "l"(v));
    return lo + hi;
}
__device__ __forceinline__ u64 pack2(float lo, float hi) {
    u64 d;
    asm("mov.b64 %0, {%1, %2};" : "=l"(d) : "f"(lo), "f"(hi));
    return d;
}
__device__ __forceinline__ float fsig(float x) {
    return __fdividef(1.0f, 1.0f + __expf(-x));
}
__device__ __forceinline__ float ftanh(float x) {
    const float e = __expf(-2.0f * x);
    return __fdividef(1.0f - e, 1.0f + e);
}

// ---------------------------------------------------------------------------
// Layer 0: one warp per (b, dir). Lane j owns hidden dim j.
// W_hh in registers (48 packed u64); h broadcast via parity-buffered smem.
// grid: (B/2, 2), block 64. NO min-blocks clause -> no forced spill.
// ---------------------------------------------------------------------------
__global__ void __launch_bounds__(64) gru_l0(
    const float* __restrict__ x,      // [B,T,4]
    const float* __restrict__ w_ih,   // [2,96,4]
    const float* __restrict__ w_hh,   // [2,96,32]
    const float* __restrict__ b_ih,   // [2,96]
    const float* __restrict__ b_hh)   // [2,96]
{
    __shared__ __align__(16) float sh[2][2][32];   // [warp][parity][lane]

    const int warp = threadIdx.x >> 5;
    const int j    = threadIdx.x & 31;
    const int dir  = blockIdx.y;
    const int b    = blockIdx.x * 2 + warp;

    // recurrent weights, packed pairs (rows of 32 floats = 16 u64)
    const u64* w64 = (const u64*)w_hh;
    u64 wr2[16], wz2[16], wn2[16];
    {
        const int rb = (dir * GG + j) * 16;
        const int zb = (dir * GG + 32 + j) * 16;
        const int nb = (dir * GG + 64 + j) * 16;
        #pragma unroll
        for (int m = 0; m < 16; m++) {
            wr2[m] = w64[rb + m];
            wz2[m] = w64[zb + m];
            wn2[m] = w64[nb + m];
        }
    }
    // input-projection weights (rows of 4 floats = 2 u64)
    const u64* wi64 = (const u64*)w_ih;
    const u64 wrA = wi64[(dir * GG + j) * 2],      wrB = wi64[(dir * GG + j) * 2 + 1];
    const u64 wzA = wi64[(dir * GG + 32 + j) * 2], wzB = wi64[(dir * GG + 32 + j) * 2 + 1];
    const u64 wnA = wi64[(dir * GG + 64 + j) * 2], wnB = wi64[(dir * GG + 64 + j) * 2 + 1];

    // biases pre-packed into accumulator inits
    const u64 br2 = pack2(b_ih[dir * GG + j]      + b_hh[dir * GG + j],      0.0f);
    const u64 bz2 = pack2(b_ih[dir * GG + 32 + j] + b_hh[dir * GG + 32 + j], 0.0f);
    const u64 bx2 = pack2(b_ih[dir * GG + 64 + j], 0.0f);
    const u64 bh2 = pack2(b_hh[dir * GG + 64 + j], 0.0f);

    float h = 0.0f;
    const int tstep = dir ? -1 : 1;
    int t = dir ? (TT - 1) : 0;

    const ulonglong2* xb2 = (const ulonglong2*)(x + (size_t)b * TT * II);
    float* ob = g_h1 + (size_t)b * TT * 2 * HH + dir * HH + j;

    ulonglong2 xx = xb2[t];   // x row for current t (2 packed pairs)

    for (int s = 0; s < TT; ++s, t += tstep) {
        // prefetch next step's input (clamped on last iter; always valid)
        const int tl = (s == TT - 1) ? t : (t + tstep);
        const ulonglong2 xnx = xb2[tl];

        const int par = s & 1;
        sh[warp][par][j] = h;
        __syncwarp();

        // input projection folded into chain-a accumulators
        u64 ra = fma2(wrA, xx.x, fma2(wrB, xx.y, br2));
        u64 za = fma2(wzA, xx.x, fma2(wzB, xx.y, bz2));
        u64 xa = fma2(wnA, xx.x, fma2(wnB, xx.y, bx2));
        u64 na = bh2;
        u64 rb = 0ULL, zb = 0ULL, nb = 0ULL;

        const ulonglong2* hv = (const ulonglong2*)sh[warp][par];
        #pragma unroll
        for (int q = 0; q < 8; q++) {
            const ulonglong2 hp = hv[q];
            ra = fma2(wr2[2 * q],     hp.x, ra);
            za = fma2(wz2[2 * q],     hp.x, za);
            na = fma2(wn2[2 * q],     hp.x, na);
            rb = fma2(wr2[2 * q + 1], hp.y, rb);
            zb = fma2(wz2[2 * q + 1], hp.y, zb);
            nb = fma2(wn2[2 * q + 1], hp.y, nb);
        }

        const float r = fsig(sum2(add2(ra, rb)));
        const float z = fsig(sum2(add2(za, zb)));
        const float n = ftanh(sum2(xa) + r * sum2(add2(na, nb)));
        h = n + z * (h - n);

        ob[(size_t)t * 2 * HH] = h;
        xx = xnx;
    }
}

// ---------------------------------------------------------------------------
// Layer 1 input projection: xg[dir][b][t][96] = h1[b][t] @ W_ih^T + b_ih
// Gate-split: one warp per (b, dir, gate, t-chunk of 128). 64 weight regs.
// Fully independent warps. block 128, grid 6144.
// ---------------------------------------------------------------------------
__global__ void __launch_bounds__(128) gru_l1_xg(
    const float* __restrict__ w_ih,   // [2,96,64]
    const float* __restrict__ b_ih)   // [2,96]
{
    __shared__ __align__(16) float sh[4][2][64];   // [warp][parity][k]

    const int w = threadIdx.x >> 5;
    const int j = threadIdx.x & 31;

    // task = ((b*2 + dir)*3 + gate)*4 + tc
    const int task = blockIdx.x * 4 + w;
    const int tc   = task & 3;
    const int rest = task >> 2;
    const int gate = rest % 3;
    const int bd   = rest / 3;
    const int dir  = bd & 1;
    const int b    = bd >> 1;

    // this lane's weight row (64 floats = 32 u64)
    const u64* w64 = (const u64*)w_ih;
    u64 wg[32];
    {
        const int rb = (dir * GG + gate * 32 + j) * 32;
        #pragma unroll
        for (int m = 0; m < 32; m++) wg[m] = w64[rb + m];
    }
    const float bias = b_ih[dir * GG + gate * 32 + j];

    const float* ib = g_h1 + (size_t)b * TT * 2 * HH;
    float* xo = g_xg + (((size_t)dir * BB + b) * TT) * GG + gate * 32 + j;

    const int t0 = tc * (TT / 4);
    float a = ib[(size_t)t0 * 64 + j];
    float c = ib[(size_t)t0 * 64 + 32 + j];

    for (int s = 0; s < TT / 4; ++s) {
        const int t  = t0 + s;
        const int tl = (s == TT / 4 - 1) ? t : (t + 1);
        const float an = ib[(size_t)tl * 64 + j];
        const float cn = ib[(size_t)tl * 64 + 32 + j];

        const int par = s & 1;
        sh[w][par][j]      = a;
        sh[w][par][j + 32] = c;
        __syncwarp();

        u64 p0 = 0ULL, p1 = 0ULL;
        const ulonglong2* hv = (const ulonglong2*)sh[w][par];
        #pragma unroll
        for (int q = 0; q < 16; q++) {
            const ulonglong2 hp = hv[q];
            p0 = fma2(wg[2 * q],     hp.x, p0);
            p1 = fma2(wg[2 * q + 1], hp.y, p1);
        }

        xo[(size_t)t * GG] = bias + sum2(add2(p0, p1));
        a = an; c = cn;
    }
}

// ---------------------------------------------------------------------------
// Layer 1 recurrence: reads precomputed xg (prefetched). grid (B/2,2), block 64.
// ---------------------------------------------------------------------------
__global__ void __launch_bounds__(64) gru_l1_rec(
    const float* __restrict__ w_hh,   // [2,96,32]
    const float* __restrict__ b_hh)   // [2,96]
{
    __shared__ __align__(16) float sh[2][2][32];

    const int warp = threadIdx.x >> 5;
    const int j    = threadIdx.x & 31;
    const int dir  = blockIdx.y;
    const int b    = blockIdx.x * 2 + warp;

    const u64* w64 = (const u64*)w_hh;
    u64 wr2[16], wz2[16], wn2[16];
    {
        const int rb = (dir * GG + j) * 16;
        const int zb = (dir * GG + 32 + j) * 16;
        const int nb = (dir * GG + 64 + j) * 16;
        #pragma unroll
        for (int m = 0; m < 16; m++) {
            wr2[m] = w64[rb + m];
            wz2[m] = w64[zb + m];
            wn2[m] = w64[nb + m];
        }
    }
    const float brh = b_hh[dir * GG + j];
    const float bzh = b_hh[dir * GG + 32 + j];
    const u64   bh2 = pack2(b_hh[dir * GG + 64 + j], 0.0f);

    float h = 0.0f;
    const int tstep = dir ? -1 : 1;
    int t = dir ? (TT - 1) : 0;

    const float* xgb = g_xg + (((size_t)dir * BB + b) * TT) * GG;
    float* ob = g_out + (size_t)b * TT * 2 * HH + dir * HH + j;

    // prefetch first step's gate inputs
    float xr = xgb[(size_t)t * GG + j];
    float xz = xgb[(size_t)t * GG + 32 + j];
    float xn = xgb[(size_t)t * GG + 64 + j];

    for (int s = 0; s < TT; ++s, t += tstep) {
        const int tl = (s == TT - 1) ? t : (t + tstep);
        const float xr_n = xgb[(size_t)tl * GG + j];
        const float xz_n = xgb[(size_t)tl * GG + 32 + j];
        const float xn_n = xgb[(size_t)tl * GG + 64 + j];

        const int par = s & 1;
        sh[warp][par][j] = h;
        __syncwarp();

        u64 ra = pack2(xr + brh, 0.0f);
        u64 za = pack2(xz + bzh, 0.0f);
        u64 na = bh2;
        u64 rb = 0ULL, zb = 0ULL, nb = 0ULL;

        const ulonglong2* hv = (const ulonglong2*)sh[warp][par];
        #pragma unroll
        for (int q = 0; q < 8; q++) {
            const ulonglong2 hp = hv[q];
            ra = fma2(wr2[2 * q],     hp.x, ra);
            za = fma2(wz2[2 * q],     hp.x, za);
            na = fma2(wn2[2 * q],     hp.x, na);
            rb = fma2(wr2[2 * q + 1], hp.y, rb);
            zb = fma2(wz2[2 * q + 1], hp.y, zb);
            nb = fma2(wn2[2 * q + 1], hp.y, nb);
        }

        const float r = fsig(sum2(add2(ra, rb)));
        const float z = fsig(sum2(add2(za, zb)));
        const float n = ftanh(xn + r * sum2(add2(na, nb)));
        h = n + z * (h - n);

        ob[(size_t)t * 2 * HH] = h;
        xr = xr_n; xz = xz_n; xn = xn_n;
    }
}

// ---------------------------------------------------------------------------
// Epilogue: attention-softmax pooling over T + sigmoid FC. One block per batch.
// ---------------------------------------------------------------------------
__global__ void __launch_bounds__(256) attn_fc_kernel(
    const float* __restrict__ attn_w,  // [1,64]
    const float* __restrict__ fc_w,    // [1,64]
    const float* __restrict__ fc_b,    // [1]
    float* __restrict__ y)             // [B,1]
{
    __shared__ float sl[TT];
    __shared__ float saw[64], sfw[64];
    __shared__ float redm[8], reds[8];
    __shared__ float sctx[64];

    const int b    = blockIdx.x;
    const int tid  = threadIdx.x;
    const int warp = tid >> 5;
    const int lane = tid & 31;

    if (tid < 64) {
        saw[tid]  = attn_w[tid];
        sfw[tid]  = fc_w[tid];
        sctx[tid] = 0.0f;
    }
    __syncthreads();

    const float* ob = g_out + (size_t)b * TT * 64;

    // logits (attn_b constant over T -> cancels in softmax)
    for (int t = warp; t < TT; t += 8) {
        const float* p = ob + (size_t)t * 64;
        float v = p[lane] * saw[lane] + p[lane + 32] * saw[lane + 32];
        #pragma unroll
        for (int o = 16; o; o >>= 1) v += __shfl_xor_sync(0xffffffffu, v, o);
        if (lane == 0) sl[t] = v;
    }
    __syncthreads();

    // max
    float m = -INFINITY;
    for (int t = tid; t < TT; t += 256) m = fmaxf(m, sl[t]);
    #pragma unroll
    for (int o = 16; o; o >>= 1) m = fmaxf(m, __shfl_xor_sync(0xffffffffu, m, o));
    if (lane == 0) redm[warp] = m;
    __syncthreads();
    float mm = redm[0];
    #pragma unroll
    for (int w = 1; w < 8; w++) mm = fmaxf(mm, redm[w]);

    // exp + sum
    float ssum = 0.0f;
    for (int t = tid; t < TT; t += 256) {
        float p = __expf(sl[t] - mm);
        sl[t] = p;
        ssum += p;
    }
    #pragma unroll
    for (int o = 16; o; o >>= 1) ssum += __shfl_xor_sync(0xffffffffu, ssum, o);
    if (lane == 0) reds[warp] = ssum;
    __syncthreads();

    // ctx accumulation (unnormalized)
    float c0 = 0.0f, c1 = 0.0f;
    for (int t = warp; t < TT; t += 8) {
        float p = sl[t];
        const float* q = ob + (size_t)t * 64;
        c0 += p * q[lane];
        c1 += p * q[lane + 32];
    }
    atomicAdd(&sctx[lane], c0);
    atomicAdd(&sctx[lane + 32], c1);
    __syncthreads();

    if (tid < 32) {
        float Z = reds[0];
        #pragma unroll
        for (int w = 1; w < 8; w++) Z += reds[w];
        float v = sctx[lane] * sfw[lane] + sctx[lane + 32] * sfw[lane + 32];
        #pragma unroll
        for (int o = 16; o; o >>= 1) v += __shfl_xor_sync(0xffffffffu, v, o);
        if (lane == 0) {
            y[b] = __fdividef(1.0f, 1.0f + __expf(-(v / Z + fc_b[0])));
        }
    }
}

extern "C" void kernel_launch(void* const* d_in, const int* in_sizes, int n_in,
                              void* d_out, int out_size) {
    const float* x       = (const float*)d_in[0];
    const float* w_ih_l0 = (const float*)d_in[1];
    const float* w_hh_l0 = (const float*)d_in[2];
    const float* b_ih_l0 = (const float*)d_in[3];
    const float* b_hh_l0 = (const float*)d_in[4];
    const float* w_ih_l1 = (const float*)d_in[5];
    const float* w_hh_l1 = (const float*)d_in[6];
    const float* b_ih_l1 = (const float*)d_in[7];
    const float* b_hh_l1 = (const float*)d_in[8];
    const float* attn_w  = (const float*)d_in[9];
    // d_in[10] = attn_b (cancels in softmax)
    const float* fc_w    = (const float*)d_in[11];
    const float* fc_b    = (const float*)d_in[12];
    float* y = (float*)d_out;

    gru_l0    <<<dim3(BB / 2, 2), 64>>>(x, w_ih_l0, w_hh_l0, b_ih_l0, b_hh_l0);
    gru_l1_xg <<<(BB * 2 * 3 * 4) / 4, 128>>>(w_ih_l1, b_ih_l1);
    gru_l1_rec<<<dim3(BB / 2, 2), 64>>>(w_hh_l1, b_hh_l1);
    attn_fc_kernel<<<BB, 256>>>(attn_w, fc_w, fc_b, y);
}

// round 8
// speedup vs baseline: 2.0662x; 1.0435x over previous
#include <cuda_runtime.h>
#include <math.h>

#define BB 1024
#define TT 512
#define II 4
#define HH 32
#define GG 96   // 3*H

typedef unsigned long long u64;

// Scratch sequence buffers (allocation-free rule: __device__ globals).
__device__ float g_h1 [(size_t)BB * TT * 2 * HH];   // layer0 out [b][t][dir*32+j]
__device__ float g_xg [(size_t)2 * BB * TT * GG];   // layer1 input proj [dir][b][t][96]
__device__ float g_out[(size_t)BB * TT * 2 * HH];   // layer1 out

__device__ __forceinline__ u64 fma2(u64 a, u64 b, u64 c) {
    u64 d;
    asm("fma.rn.f32x2 %0, %1, %2, %3;" : "=l"(d) : "l"(a), "l"(b), "l"(c));
    return d;
}
__device__ __forceinline__ u64 add2(u64 a, u64 b) {
    u64 d;
    asm("add.rn.f32x2 %0, %1, %2;" : "=l"(d) : "l"(a), "l"(b));
    return d;
}
__device__ __forceinline__ float sum2(u64 v) {
    float lo, hi;
    asm("mov.b64 {%0, %1}, %2;" : "=f"(lo), "=f"(hi) : "l"(v));
    return lo + hi;
}
__device__ __forceinline__ u64 pack2(float lo, float hi) {
    u64 d;
    asm("mov.b64 %0, {%1, %2};" : "=l"(d) : "f"(lo), "f"(hi));
    return d;
}
__device__ __forceinline__ float frcp(float x) {
    float y;
    asm("rcp.approx.f32 %0, %1;" : "=f"(y) : "f"(x));
    return y;
}
__device__ __forceinline__ float fsig(float x) {
    return frcp(1.0f + __expf(-x));
}
__device__ __forceinline__ float ftanh(float x) {
    // 1 - 2/(e^{2x}+1)
    const float e = __expf(2.0f * x);
    return fmaf(-2.0f, frcp(e + 1.0f), 1.0f);
}

// ---------------------------------------------------------------------------
// Layer 0: one warp handles TWO sequences (b0, b0+1) of the same direction.
// Weights shared in registers across the two sequences (2x ILP, same RF cost).
// grid: (B/4, 2), block 64.
// ---------------------------------------------------------------------------
__global__ void __launch_bounds__(64) gru_l0(
    const float* __restrict__ x,      // [B,T,4]
    const float* __restrict__ w_ih,   // [2,96,4]
    const float* __restrict__ w_hh,   // [2,96,32]
    const float* __restrict__ b_ih,   // [2,96]
    const float* __restrict__ b_hh)   // [2,96]
{
    __shared__ __align__(16) float sh[2][2][2][32];   // [warp][seq][parity][lane]

    const int warp = threadIdx.x >> 5;
    const int j    = threadIdx.x & 31;
    const int dir  = blockIdx.y;
    const int b0   = blockIdx.x * 4 + warp * 2;

    // recurrent weights, packed pairs (rows of 32 floats = 16 u64)
    const u64* w64 = (const u64*)w_hh;
    u64 wr2[16], wz2[16], wn2[16];
    {
        const int rb = (dir * GG + j) * 16;
        const int zb = (dir * GG + 32 + j) * 16;
        const int nb = (dir * GG + 64 + j) * 16;
        #pragma unroll
        for (int m = 0; m < 16; m++) {
            wr2[m] = w64[rb + m];
            wz2[m] = w64[zb + m];
            wn2[m] = w64[nb + m];
        }
    }
    // input-projection weights (rows of 4 floats = 2 u64)
    const u64* wi64 = (const u64*)w_ih;
    const u64 wrA = wi64[(dir * GG + j) * 2],      wrB = wi64[(dir * GG + j) * 2 + 1];
    const u64 wzA = wi64[(dir * GG + 32 + j) * 2], wzB = wi64[(dir * GG + 32 + j) * 2 + 1];
    const u64 wnA = wi64[(dir * GG + 64 + j) * 2], wnB = wi64[(dir * GG + 64 + j) * 2 + 1];

    const u64 br2 = pack2(b_ih[dir * GG + j]      + b_hh[dir * GG + j],      0.0f);
    const u64 bz2 = pack2(b_ih[dir * GG + 32 + j] + b_hh[dir * GG + 32 + j], 0.0f);
    const u64 bx2 = pack2(b_ih[dir * GG + 64 + j], 0.0f);
    const u64 bh2 = pack2(b_hh[dir * GG + 64 + j], 0.0f);

    float h0 = 0.0f, h1 = 0.0f;
    const int tstep = dir ? -1 : 1;
    int t = dir ? (TT - 1) : 0;

    const ulonglong2* xA = (const ulonglong2*)(x + (size_t)b0 * TT * II);
    const ulonglong2* xB = xA + TT;
    float* oA = g_h1 + (size_t)b0 * TT * 2 * HH + dir * HH + j;
    float* oB = oA + (size_t)TT * 2 * HH;

    ulonglong2 xx0 = xA[t];
    ulonglong2 xx1 = xB[t];

    for (int s = 0; s < TT; ++s, t += tstep) {
        const int tl = (s == TT - 1) ? t : (t + tstep);
        const ulonglong2 xn0 = xA[tl];
        const ulonglong2 xn1 = xB[tl];

        const int par = s & 1;
        sh[warp][0][par][j] = h0;
        sh[warp][1][par][j] = h1;
        __syncwarp();

        u64 ra0 = fma2(wrA, xx0.x, fma2(wrB, xx0.y, br2));
        u64 za0 = fma2(wzA, xx0.x, fma2(wzB, xx0.y, bz2));
        u64 xa0 = fma2(wnA, xx0.x, fma2(wnB, xx0.y, bx2));
        u64 ra1 = fma2(wrA, xx1.x, fma2(wrB, xx1.y, br2));
        u64 za1 = fma2(wzA, xx1.x, fma2(wzB, xx1.y, bz2));
        u64 xa1 = fma2(wnA, xx1.x, fma2(wnB, xx1.y, bx2));
        u64 na0 = bh2, na1 = bh2;
        u64 rb0 = 0ULL, zb0 = 0ULL, nb0 = 0ULL;
        u64 rb1 = 0ULL, zb1 = 0ULL, nb1 = 0ULL;

        const ulonglong2* h0v = (const ulonglong2*)sh[warp][0][par];
        const ulonglong2* h1v = (const ulonglong2*)sh[warp][1][par];
        #pragma unroll
        for (int q = 0; q < 8; q++) {
            const ulonglong2 hp0 = h0v[q];
            const ulonglong2 hp1 = h1v[q];
            ra0 = fma2(wr2[2 * q],     hp0.x, ra0);
            za0 = fma2(wz2[2 * q],     hp0.x, za0);
            na0 = fma2(wn2[2 * q],     hp0.x, na0);
            ra1 = fma2(wr2[2 * q],     hp1.x, ra1);
            za1 = fma2(wz2[2 * q],     hp1.x, za1);
            na1 = fma2(wn2[2 * q],     hp1.x, na1);
            rb0 = fma2(wr2[2 * q + 1], hp0.y, rb0);
            zb0 = fma2(wz2[2 * q + 1], hp0.y, zb0);
            nb0 = fma2(wn2[2 * q + 1], hp0.y, nb0);
            rb1 = fma2(wr2[2 * q + 1], hp1.y, rb1);
            zb1 = fma2(wz2[2 * q + 1], hp1.y, zb1);
            nb1 = fma2(wn2[2 * q + 1], hp1.y, nb1);
        }

        const float r0 = fsig(sum2(add2(ra0, rb0)));
        const float r1 = fsig(sum2(add2(ra1, rb1)));
        const float z0 = fsig(sum2(add2(za0, zb0)));
        const float z1 = fsig(sum2(add2(za1, zb1)));
        const float n0 = ftanh(sum2(xa0) + r0 * sum2(add2(na0, nb0)));
        const float n1 = ftanh(sum2(xa1) + r1 * sum2(add2(na1, nb1)));
        h0 = n0 + z0 * (h0 - n0);
        h1 = n1 + z1 * (h1 - n1);

        oA[(size_t)t * 2 * HH] = h0;
        oB[(size_t)t * 2 * HH] = h1;
        xx0 = xn0; xx1 = xn1;
    }
}

// ---------------------------------------------------------------------------
// Layer 1 input projection: xg[dir][b][t][96] = h1[b][t] @ W_ih^T + b_ih
// Gate-split warps; each warp processes TWO timesteps per iteration
// (weights reused, 2 independent accumulator sets). block 128, grid 1536.
// ---------------------------------------------------------------------------
__global__ void __launch_bounds__(128) gru_l1_xg(
    const float* __restrict__ w_ih,   // [2,96,64]
    const float* __restrict__ b_ih)   // [2,96]
{
    __shared__ __align__(16) u64 sx[4][2][64];   // [warp][parity][2 rows x 32 u64]

    const int w = threadIdx.x >> 5;
    const int j = threadIdx.x & 31;

    const int task = blockIdx.x * 4 + w;     // (b*2 + dir)*3 + gate
    const int gate = task % 3;
    const int bd   = task / 3;
    const int dir  = bd & 1;
    const int b    = bd >> 1;

    const u64* w64 = (const u64*)w_ih;
    u64 wg[32];
    {
        const int rb = (dir * GG + gate * 32 + j) * 32;
        #pragma unroll
        for (int m = 0; m < 32; m++) wg[m] = w64[rb + m];
    }
    const float bias = b_ih[dir * GG + gate * 32 + j];

    const u64* ib64 = (const u64*)g_h1 + (size_t)b * TT * 32;   // row t -> ib64[t*32+j]
    float* xo = g_xg + (((size_t)dir * BB + b) * TT) * GG + gate * 32 + j;

    u64 a0 = ib64[j];           // row 0
    u64 a1 = ib64[32 + j];      // row 1

    for (int s = 0; s < TT / 2; ++s) {
        const int t  = 2 * s;
        const int tn = (s == TT / 2 - 1) ? t : (t + 2);
        const u64 p0 = ib64[(size_t)tn * 32 + j];
        const u64 p1 = ib64[(size_t)(tn + 1) * 32 + j];

        const int par = s & 1;
        sx[w][par][j]      = a0;
        sx[w][par][32 + j] = a1;
        __syncwarp();

        u64 A0 = 0ULL, A1 = 0ULL, B0 = 0ULL, B1 = 0ULL;
        const ulonglong2* r0 = (const ulonglong2*)&sx[w][par][0];
        const ulonglong2* r1 = (const ulonglong2*)&sx[w][par][32];
        #pragma unroll
        for (int q = 0; q < 16; q++) {
            const ulonglong2 u = r0[q];
            const ulonglong2 v = r1[q];
            A0 = fma2(wg[2 * q],     u.x, A0);
            B0 = fma2(wg[2 * q],     v.x, B0);
            A1 = fma2(wg[2 * q + 1], u.y, A1);
            B1 = fma2(wg[2 * q + 1], v.y, B1);
        }

        xo[(size_t)t * GG]       = bias + sum2(add2(A0, A1));
        xo[(size_t)(t + 1) * GG] = bias + sum2(add2(B0, B1));
        a0 = p0; a1 = p1;
    }
}

// ---------------------------------------------------------------------------
// Layer 1 recurrence: TWO sequences per warp, shared weights. grid (B/4,2).
// ---------------------------------------------------------------------------
__global__ void __launch_bounds__(64) gru_l1_rec(
    const float* __restrict__ w_hh,   // [2,96,32]
    const float* __restrict__ b_hh)   // [2,96]
{
    __shared__ __align__(16) float sh[2][2][2][32];

    const int warp = threadIdx.x >> 5;
    const int j    = threadIdx.x & 31;
    const int dir  = blockIdx.y;
    const int b0   = blockIdx.x * 4 + warp * 2;

    const u64* w64 = (const u64*)w_hh;
    u64 wr2[16], wz2[16], wn2[16];
    {
        const int rb = (dir * GG + j) * 16;
        const int zb = (dir * GG + 32 + j) * 16;
        const int nb = (dir * GG + 64 + j) * 16;
        #pragma unroll
        for (int m = 0; m < 16; m++) {
            wr2[m] = w64[rb + m];
            wz2[m] = w64[zb + m];
            wn2[m] = w64[nb + m];
        }
    }
    const float brh = b_hh[dir * GG + j];
    const float bzh = b_hh[dir * GG + 32 + j];
    const u64   bh2 = pack2(b_hh[dir * GG + 64 + j], 0.0f);

    float h0 = 0.0f, h1 = 0.0f;
    const int tstep = dir ? -1 : 1;
    int t = dir ? (TT - 1) : 0;

    const float* xgA = g_xg + (((size_t)dir * BB + b0) * TT) * GG;
    const float* xgB = xgA + (size_t)TT * GG;
    float* oA = g_out + (size_t)b0 * TT * 2 * HH + dir * HH + j;
    float* oB = oA + (size_t)TT * 2 * HH;

    float xr0 = xgA[(size_t)t * GG + j];
    float xz0 = xgA[(size_t)t * GG + 32 + j];
    float xn0 = xgA[(size_t)t * GG + 64 + j];
    float xr1 = xgB[(size_t)t * GG + j];
    float xz1 = xgB[(size_t)t * GG + 32 + j];
    float xn1 = xgB[(size_t)t * GG + 64 + j];

    for (int s = 0; s < TT; ++s, t += tstep) {
        const int tl = (s == TT - 1) ? t : (t + tstep);
        const float xr0n = xgA[(size_t)tl * GG + j];
        const float xz0n = xgA[(size_t)tl * GG + 32 + j];
        const float xn0n = xgA[(size_t)tl * GG + 64 + j];
        const float xr1n = xgB[(size_t)tl * GG + j];
        const float xz1n = xgB[(size_t)tl * GG + 32 + j];
        const float xn1n = xgB[(size_t)tl * GG + 64 + j];

        const int par = s & 1;
        sh[warp][0][par][j] = h0;
        sh[warp][1][par][j] = h1;
        __syncwarp();

        u64 ra0 = pack2(xr0 + brh, 0.0f);
        u64 za0 = pack2(xz0 + bzh, 0.0f);
        u64 ra1 = pack2(xr1 + brh, 0.0f);
        u64 za1 = pack2(xz1 + bzh, 0.0f);
        u64 na0 = bh2, na1 = bh2;
        u64 rb0 = 0ULL, zb0 = 0ULL, nb0 = 0ULL;
        u64 rb1 = 0ULL, zb1 = 0ULL, nb1 = 0ULL;

        const ulonglong2* h0v = (const ulonglong2*)sh[warp][0][par];
        const ulonglong2* h1v = (const ulonglong2*)sh[warp][1][par];
        #pragma unroll
        for (int q = 0; q < 8; q++) {
            const ulonglong2 hp0 = h0v[q];
            const ulonglong2 hp1 = h1v[q];
            ra0 = fma2(wr2[2 * q],     hp0.x, ra0);
            za0 = fma2(wz2[2 * q],     hp0.x, za0);
            na0 = fma2(wn2[2 * q],     hp0.x, na0);
            ra1 = fma2(wr2[2 * q],     hp1.x, ra1);
            za1 = fma2(wz2[2 * q],     hp1.x, za1);
            na1 = fma2(wn2[2 * q],     hp1.x, na1);
            rb0 = fma2(wr2[2 * q + 1], hp0.y, rb0);
            zb0 = fma2(wz2[2 * q + 1], hp0.y, zb0);
            nb0 = fma2(wn2[2 * q + 1], hp0.y, nb0);
            rb1 = fma2(wr2[2 * q + 1], hp1.y, rb1);
            zb1 = fma2(wz2[2 * q + 1], hp1.y, zb1);
            nb1 = fma2(wn2[2 * q + 1], hp1.y, nb1);
        }

        const float r0 = fsig(sum2(add2(ra0, rb0)));
        const float r1 = fsig(sum2(add2(ra1, rb1)));
        const float z0 = fsig(sum2(add2(za0, zb0)));
        const float z1 = fsig(sum2(add2(za1, zb1)));
        const float n0 = ftanh(xn0 + r0 * sum2(add2(na0, nb0)));
        const float n1 = ftanh(xn1 + r1 * sum2(add2(na1, nb1)));
        h0 = n0 + z0 * (h0 - n0);
        h1 = n1 + z1 * (h1 - n1);

        oA[(size_t)t * 2 * HH] = h0;
        oB[(size_t)t * 2 * HH] = h1;
        xr0 = xr0n; xz0 = xz0n; xn0 = xn0n;
        xr1 = xr1n; xz1 = xz1n; xn1 = xn1n;
    }
}

// ---------------------------------------------------------------------------
// Epilogue: attention-softmax pooling over T + sigmoid FC. One block per batch.
// ---------------------------------------------------------------------------
__global__ void __launch_bounds__(256) attn_fc_kernel(
    const float* __restrict__ attn_w,  // [1,64]
    const float* __restrict__ fc_w,    // [1,64]
    const float* __restrict__ fc_b,    // [1]
    float* __restrict__ y)             // [B,1]
{
    __shared__ float sl[TT];
    __shared__ float saw[64], sfw[64];
    __shared__ float redm[8], reds[8];
    __shared__ float sctx[64];

    const int b    = blockIdx.x;
    const int tid  = threadIdx.x;
    const int warp = tid >> 5;
    const int lane = tid & 31;

    if (tid < 64) {
        saw[tid]  = attn_w[tid];
        sfw[tid]  = fc_w[tid];
        sctx[tid] = 0.0f;
    }
    __syncthreads();

    const float* ob = g_out + (size_t)b * TT * 64;

    for (int t = warp; t < TT; t += 8) {
        const float* p = ob + (size_t)t * 64;
        float v = p[lane] * saw[lane] + p[lane + 32] * saw[lane + 32];
        #pragma unroll
        for (int o = 16; o; o >>= 1) v += __shfl_xor_sync(0xffffffffu, v, o);
        if (lane == 0) sl[t] = v;
    }
    __syncthreads();

    float m = -INFINITY;
    for (int t = tid; t < TT; t += 256) m = fmaxf(m, sl[t]);
    #pragma unroll
    for (int o = 16; o; o >>= 1) m = fmaxf(m, __shfl_xor_sync(0xffffffffu, m, o));
    if (lane == 0) redm[warp] = m;
    __syncthreads();
    float mm = redm[0];
    #pragma unroll
    for (int w = 1; w < 8; w++) mm = fmaxf(mm, redm[w]);

    float ssum = 0.0f;
    for (int t = tid; t < TT; t += 256) {
        float p = __expf(sl[t] - mm);
        sl[t] = p;
        ssum += p;
    }
    #pragma unroll
    for (int o = 16; o; o >>= 1) ssum += __shfl_xor_sync(0xffffffffu, ssum, o);
    if (lane == 0) reds[warp] = ssum;
    __syncthreads();

    float c0 = 0.0f, c1 = 0.0f;
    for (int t = warp; t < TT; t += 8) {
        float p = sl[t];
        const float* q = ob + (size_t)t * 64;
        c0 += p * q[lane];
        c1 += p * q[lane + 32];
    }
    atomicAdd(&sctx[lane], c0);
    atomicAdd(&sctx[lane + 32], c1);
    __syncthreads();

    if (tid < 32) {
        float Z = reds[0];
        #pragma unroll
        for (int w = 1; w < 8; w++) Z += reds[w];
        float v = sctx[lane] * sfw[lane] + sctx[lane + 32] * sfw[lane + 32];
        #pragma unroll
        for (int o = 16; o; o >>= 1) v += __shfl_xor_sync(0xffffffffu, v, o);
        if (lane == 0) {
            y[b] = frcp(1.0f + __expf(-(v / Z + fc_b[0])));
        }
    }
}

extern "C" void kernel_launch(void* const* d_in, const int* in_sizes, int n_in,
                              void* d_out, int out_size) {
    const float* x       = (const float*)d_in[0];
    const float* w_ih_l0 = (const float*)d_in[1];
    const float* w_hh_l0 = (const float*)d_in[2];
    const float* b_ih_l0 = (const float*)d_in[3];
    const float* b_hh_l0 = (const float*)d_in[4];
    const float* w_ih_l1 = (const float*)d_in[5];
    const float* w_hh_l1 = (const float*)d_in[6];
    const float* b_ih_l1 = (const float*)d_in[7];
    const float* b_hh_l1 = (const float*)d_in[8];
    const float* attn_w  = (const float*)d_in[9];
    // d_in[10] = attn_b (cancels in softmax)
    const float* fc_w    = (const float*)d_in[11];
    const float* fc_b    = (const float*)d_in[12];
    float* y = (float*)d_out;

    gru_l0    <<<dim3(BB / 4, 2), 64>>>(x, w_ih_l0, w_hh_l0, b_ih_l0, b_hh_l0);
    gru_l1_xg <<<(BB * 2 * 3) / 4, 128>>>(w_ih_l1, b_ih_l1);
    gru_l1_rec<<<dim3(BB / 4, 2), 64>>>(w_hh_l1, b_hh_l1);
    attn_fc_kernel<<<BB, 256>>>(attn_w, fc_w, fc_b, y);
}

// round 9
// speedup vs baseline: 2.3013x; 1.1138x over previous
#include <cuda_runtime.h>
#include <cuda_fp16.h>
#include <math.h>

#define BB 1024
#define TT 512
#define II 4
#define HH 32
#define GG 96   // 3*H

typedef unsigned long long u64;

// Scratch sequence buffers (allocation-free rule: __device__ globals).
__device__ float  g_h1 [(size_t)BB * TT * 2 * HH];   // layer0 out [b][t][dir*32+j]
__device__ __half g_xg [(size_t)2 * BB * TT * GG];   // layer1 input proj (fp16) [dir][b][t][96]
__device__ float  g_out[(size_t)BB * TT * 2 * HH];   // layer1 out

__device__ __forceinline__ u64 fma2(u64 a, u64 b, u64 c) {
    u64 d;
    asm("fma.rn.f32x2 %0, %1, %2, %3;" : "=l"(d) : "l"(a), "l"(b), "l"(c));
    return d;
}
__device__ __forceinline__ u64 add2(u64 a, u64 b) {
    u64 d;
    asm("add.rn.f32x2 %0, %1, %2;" : "=l"(d) : "l"(a), "l"(b));
    return d;
}
__device__ __forceinline__ float sum2(u64 v) {
    float lo, hi;
    asm("mov.b64 {%0, %1}, %2;" : "=f"(lo), "=f"(hi) : "l"(v));
    return lo + hi;
}
__device__ __forceinline__ u64 pack2(float lo, float hi) {
    u64 d;
    asm("mov.b64 %0, {%1, %2};" : "=l"(d) : "f"(lo), "f"(hi));
    return d;
}
__device__ __forceinline__ float frcp(float x) {
    float y;
    asm("rcp.approx.f32 %0, %1;" : "=f"(y) : "f"(x));
    return y;
}
__device__ __forceinline__ float fsig(float x) {
    return frcp(1.0f + __expf(-x));
}
__device__ __forceinline__ float ftanh(float x) {
    const float e = __expf(2.0f * x);
    return fmaf(-2.0f, frcp(e + 1.0f), 1.0f);
}
__device__ __forceinline__ __half2 u64_to_h2(u64 v) {
    float lo, hi;
    asm("mov.b64 {%0, %1}, %2;" : "=f"(lo), "=f"(hi) : "l"(v));
    return __floats2half2_rn(lo, hi);
}
__device__ __forceinline__ float h2sum(__half2 v) {
    return __low2float(v) + __high2float(v);
}

// ---------------------------------------------------------------------------
// Layer 0: one warp handles TWO sequences of the same direction (fp32).
// grid: (B/4, 2), block 64.
// ---------------------------------------------------------------------------
__global__ void __launch_bounds__(64) gru_l0(
    const float* __restrict__ x,      // [B,T,4]
    const float* __restrict__ w_ih,   // [2,96,4]
    const float* __restrict__ w_hh,   // [2,96,32]
    const float* __restrict__ b_ih,   // [2,96]
    const float* __restrict__ b_hh)   // [2,96]
{
    __shared__ __align__(16) float sh[2][2][2][32];   // [warp][seq][parity][lane]

    const int warp = threadIdx.x >> 5;
    const int j    = threadIdx.x & 31;
    const int dir  = blockIdx.y;
    const int b0   = blockIdx.x * 4 + warp * 2;

    const u64* w64 = (const u64*)w_hh;
    u64 wr2[16], wz2[16], wn2[16];
    {
        const int rb = (dir * GG + j) * 16;
        const int zb = (dir * GG + 32 + j) * 16;
        const int nb = (dir * GG + 64 + j) * 16;
        #pragma unroll
        for (int m = 0; m < 16; m++) {
            wr2[m] = w64[rb + m];
            wz2[m] = w64[zb + m];
            wn2[m] = w64[nb + m];
        }
    }
    const u64* wi64 = (const u64*)w_ih;
    const u64 wrA = wi64[(dir * GG + j) * 2],      wrB = wi64[(dir * GG + j) * 2 + 1];
    const u64 wzA = wi64[(dir * GG + 32 + j) * 2], wzB = wi64[(dir * GG + 32 + j) * 2 + 1];
    const u64 wnA = wi64[(dir * GG + 64 + j) * 2], wnB = wi64[(dir * GG + 64 + j) * 2 + 1];

    const u64 br2 = pack2(b_ih[dir * GG + j]      + b_hh[dir * GG + j],      0.0f);
    const u64 bz2 = pack2(b_ih[dir * GG + 32 + j] + b_hh[dir * GG + 32 + j], 0.0f);
    const u64 bx2 = pack2(b_ih[dir * GG + 64 + j], 0.0f);
    const u64 bh2 = pack2(b_hh[dir * GG + 64 + j], 0.0f);

    float h0 = 0.0f, h1 = 0.0f;
    const int tstep = dir ? -1 : 1;
    int t = dir ? (TT - 1) : 0;

    const ulonglong2* xA = (const ulonglong2*)(x + (size_t)b0 * TT * II);
    const ulonglong2* xB = xA + TT;
    float* oA = g_h1 + (size_t)b0 * TT * 2 * HH + dir * HH + j;
    float* oB = oA + (size_t)TT * 2 * HH;

    ulonglong2 xx0 = xA[t];
    ulonglong2 xx1 = xB[t];

    for (int s = 0; s < TT; ++s, t += tstep) {
        const int tl = (s == TT - 1) ? t : (t + tstep);
        const ulonglong2 xn0 = xA[tl];
        const ulonglong2 xn1 = xB[tl];

        const int par = s & 1;
        sh[warp][0][par][j] = h0;
        sh[warp][1][par][j] = h1;
        __syncwarp();

        u64 ra0 = fma2(wrA, xx0.x, fma2(wrB, xx0.y, br2));
        u64 za0 = fma2(wzA, xx0.x, fma2(wzB, xx0.y, bz2));
        u64 xa0 = fma2(wnA, xx0.x, fma2(wnB, xx0.y, bx2));
        u64 ra1 = fma2(wrA, xx1.x, fma2(wrB, xx1.y, br2));
        u64 za1 = fma2(wzA, xx1.x, fma2(wzB, xx1.y, bz2));
        u64 xa1 = fma2(wnA, xx1.x, fma2(wnB, xx1.y, bx2));
        u64 na0 = bh2, na1 = bh2;
        u64 rb0 = 0ULL, zb0 = 0ULL, nb0 = 0ULL;
        u64 rb1 = 0ULL, zb1 = 0ULL, nb1 = 0ULL;

        const ulonglong2* h0v = (const ulonglong2*)sh[warp][0][par];
        const ulonglong2* h1v = (const ulonglong2*)sh[warp][1][par];
        #pragma unroll
        for (int q = 0; q < 8; q++) {
            const ulonglong2 hp0 = h0v[q];
            const ulonglong2 hp1 = h1v[q];
            ra0 = fma2(wr2[2 * q],     hp0.x, ra0);
            za0 = fma2(wz2[2 * q],     hp0.x, za0);
            na0 = fma2(wn2[2 * q],     hp0.x, na0);
            ra1 = fma2(wr2[2 * q],     hp1.x, ra1);
            za1 = fma2(wz2[2 * q],     hp1.x, za1);
            na1 = fma2(wn2[2 * q],     hp1.x, na1);
            rb0 = fma2(wr2[2 * q + 1], hp0.y, rb0);
            zb0 = fma2(wz2[2 * q + 1], hp0.y, zb0);
            nb0 = fma2(wn2[2 * q + 1], hp0.y, nb0);
            rb1 = fma2(wr2[2 * q + 1], hp1.y, rb1);
            zb1 = fma2(wz2[2 * q + 1], hp1.y, zb1);
            nb1 = fma2(wn2[2 * q + 1], hp1.y, nb1);
        }

        const float r0 = fsig(sum2(add2(ra0, rb0)));
        const float r1 = fsig(sum2(add2(ra1, rb1)));
        const float z0 = fsig(sum2(add2(za0, zb0)));
        const float z1 = fsig(sum2(add2(za1, zb1)));
        const float n0 = ftanh(sum2(xa0) + r0 * sum2(add2(na0, nb0)));
        const float n1 = ftanh(sum2(xa1) + r1 * sum2(add2(na1, nb1)));
        h0 = n0 + z0 * (h0 - n0);
        h1 = n1 + z1 * (h1 - n1);

        oA[(size_t)t * 2 * HH] = h0;
        oB[(size_t)t * 2 * HH] = h1;
        xx0 = xn0; xx1 = xn1;
    }
}

// ---------------------------------------------------------------------------
// Layer 1 input projection in fp16 HFMA2: xg = h1 @ W_ih^T + b_ih.
// Gate-split warps; 2 timesteps/iter; weights as 32 half2 regs; fp32 combine.
// block 128, grid 1536. Output stored as __half.
// ---------------------------------------------------------------------------
__global__ void __launch_bounds__(128) gru_l1_xg(
    const float* __restrict__ w_ih,   // [2,96,64]
    const float* __restrict__ b_ih)   // [2,96]
{
    __shared__ __align__(16) __half2 sx[4][2][2][32];   // [warp][parity][row][k-pair]

    const int w = threadIdx.x >> 5;
    const int j = threadIdx.x & 31;

    const int task = blockIdx.x * 4 + w;     // (b*2 + dir)*3 + gate
    const int gate = task % 3;
    const int bd   = task / 3;
    const int dir  = bd & 1;
    const int b    = bd >> 1;

    // lane's weight row: 64 fp32 -> 32 half2 regs
    const u64* w64 = (const u64*)w_ih;
    __half2 wg[32];
    {
        const int rb = (dir * GG + gate * 32 + j) * 32;
        #pragma unroll
        for (int m = 0; m < 32; m++) wg[m] = u64_to_h2(w64[rb + m]);
    }
    const float bias = b_ih[dir * GG + gate * 32 + j];

    const u64* ib64 = (const u64*)g_h1 + (size_t)b * TT * 32;   // row t -> ib64[t*32+j]
    __half* xo = g_xg + (((size_t)dir * BB + b) * TT) * GG + gate * 32 + j;

    u64 a0 = ib64[j];           // row 0 (2 fp32 of this lane)
    u64 a1 = ib64[32 + j];      // row 1

    for (int s = 0; s < TT / 2; ++s) {
        const int t  = 2 * s;
        const int tn = (s == TT / 2 - 1) ? t : (t + 2);
        const u64 p0 = ib64[(size_t)tn * 32 + j];
        const u64 p1 = ib64[(size_t)(tn + 1) * 32 + j];

        const int par = s & 1;
        sx[w][par][0][j] = u64_to_h2(a0);
        sx[w][par][1][j] = u64_to_h2(a1);
        __syncwarp();

        __half2 A0, A1, A2, A3, B0, B1, B2, B3;
        A0 = A1 = A2 = A3 = B0 = B1 = B2 = B3 = __floats2half2_rn(0.0f, 0.0f);

        const uint4* r0 = (const uint4*)&sx[w][par][0][0];   // 8 x uint4 = 32 half2
        const uint4* r1 = (const uint4*)&sx[w][par][1][0];
        #pragma unroll
        for (int q = 0; q < 8; q++) {
            const uint4 u = r0[q];
            const uint4 v = r1[q];
            A0 = __hfma2(wg[4 * q],     *(const __half2*)&u.x, A0);
            A1 = __hfma2(wg[4 * q + 1], *(const __half2*)&u.y, A1);
            A2 = __hfma2(wg[4 * q + 2], *(const __half2*)&u.z, A2);
            A3 = __hfma2(wg[4 * q + 3], *(const __half2*)&u.w, A3);
            B0 = __hfma2(wg[4 * q],     *(const __half2*)&v.x, B0);
            B1 = __hfma2(wg[4 * q + 1], *(const __half2*)&v.y, B1);
            B2 = __hfma2(wg[4 * q + 2], *(const __half2*)&v.z, B2);
            B3 = __hfma2(wg[4 * q + 3], *(const __half2*)&v.w, B3);
        }

        const float sA = (h2sum(A0) + h2sum(A1)) + (h2sum(A2) + h2sum(A3));
        const float sB = (h2sum(B0) + h2sum(B1)) + (h2sum(B2) + h2sum(B3));
        xo[(size_t)t * GG]       = __float2half_rn(bias + sA);
        xo[(size_t)(t + 1) * GG] = __float2half_rn(bias + sB);
        a0 = p0; a1 = p1;
    }
}

// ---------------------------------------------------------------------------
// Layer 1 recurrence: TWO sequences per warp, fp32 MACs, fp16 xg inputs.
// grid (B/4, 2), block 64.
// ---------------------------------------------------------------------------
__global__ void __launch_bounds__(64) gru_l1_rec(
    const float* __restrict__ w_hh,   // [2,96,32]
    const float* __restrict__ b_hh)   // [2,96]
{
    __shared__ __align__(16) float sh[2][2][2][32];

    const int warp = threadIdx.x >> 5;
    const int j    = threadIdx.x & 31;
    const int dir  = blockIdx.y;
    const int b0   = blockIdx.x * 4 + warp * 2;

    const u64* w64 = (const u64*)w_hh;
    u64 wr2[16], wz2[16], wn2[16];
    {
        const int rb = (dir * GG + j) * 16;
        const int zb = (dir * GG + 32 + j) * 16;
        const int nb = (dir * GG + 64 + j) * 16;
        #pragma unroll
        for (int m = 0; m < 16; m++) {
            wr2[m] = w64[rb + m];
            wz2[m] = w64[zb + m];
            wn2[m] = w64[nb + m];
        }
    }
    const float brh = b_hh[dir * GG + j];
    const float bzh = b_hh[dir * GG + 32 + j];
    const u64   bh2 = pack2(b_hh[dir * GG + 64 + j], 0.0f);

    float h0 = 0.0f, h1 = 0.0f;
    const int tstep = dir ? -1 : 1;
    int t = dir ? (TT - 1) : 0;

    const __half* xgA = g_xg + (((size_t)dir * BB + b0) * TT) * GG;
    const __half* xgB = xgA + (size_t)TT * GG;
    float* oA = g_out + (size_t)b0 * TT * 2 * HH + dir * HH + j;
    float* oB = oA + (size_t)TT * 2 * HH;

    float xr0 = __half2float(xgA[(size_t)t * GG + j]);
    float xz0 = __half2float(xgA[(size_t)t * GG + 32 + j]);
    float xn0 = __half2float(xgA[(size_t)t * GG + 64 + j]);
    float xr1 = __half2float(xgB[(size_t)t * GG + j]);
    float xz1 = __half2float(xgB[(size_t)t * GG + 32 + j]);
    float xn1 = __half2float(xgB[(size_t)t * GG + 64 + j]);

    for (int s = 0; s < TT; ++s, t += tstep) {
        const int tl = (s == TT - 1) ? t : (t + tstep);
        const float xr0n = __half2float(xgA[(size_t)tl * GG + j]);
        const float xz0n = __half2float(xgA[(size_t)tl * GG + 32 + j]);
        const float xn0n = __half2float(xgA[(size_t)tl * GG + 64 + j]);
        const float xr1n = __half2float(xgB[(size_t)tl * GG + j]);
        const float xz1n = __half2float(xgB[(size_t)tl * GG + 32 + j]);
        const float xn1n = __half2float(xgB[(size_t)tl * GG + 64 + j]);

        const int par = s & 1;
        sh[warp][0][par][j] = h0;
        sh[warp][1][par][j] = h1;
        __syncwarp();

        u64 ra0 = pack2(xr0 + brh, 0.0f);
        u64 za0 = pack2(xz0 + bzh, 0.0f);
        u64 ra1 = pack2(xr1 + brh, 0.0f);
        u64 za1 = pack2(xz1 + bzh, 0.0f);
        u64 na0 = bh2, na1 = bh2;
        u64 rb0 = 0ULL, zb0 = 0ULL, nb0 = 0ULL;
        u64 rb1 = 0ULL, zb1 = 0ULL, nb1 = 0ULL;

        const ulonglong2* h0v = (const ulonglong2*)sh[warp][0][par];
        const ulonglong2* h1v = (const ulonglong2*)sh[warp][1][par];
        #pragma unroll
        for (int q = 0; q < 8; q++) {
            const ulonglong2 hp0 = h0v[q];
            const ulonglong2 hp1 = h1v[q];
            ra0 = fma2(wr2[2 * q],     hp0.x, ra0);
            za0 = fma2(wz2[2 * q],     hp0.x, za0);
            na0 = fma2(wn2[2 * q],     hp0.x, na0);
            ra1 = fma2(wr2[2 * q],     hp1.x, ra1);
            za1 = fma2(wz2[2 * q],     hp1.x, za1);
            na1 = fma2(wn2[2 * q],     hp1.x, na1);
            rb0 = fma2(wr2[2 * q + 1], hp0.y, rb0);
            zb0 = fma2(wz2[2 * q + 1], hp0.y, zb0);
            nb0 = fma2(wn2[2 * q + 1], hp0.y, nb0);
            rb1 = fma2(wr2[2 * q + 1], hp1.y, rb1);
            zb1 = fma2(wz2[2 * q + 1], hp1.y, zb1);
            nb1 = fma2(wn2[2 * q + 1], hp1.y, nb1);
        }

        const float r0 = fsig(sum2(add2(ra0, rb0)));
        const float r1 = fsig(sum2(add2(ra1, rb1)));
        const float z0 = fsig(sum2(add2(za0, zb0)));
        const float z1 = fsig(sum2(add2(za1, zb1)));
        const float n0 = ftanh(xn0 + r0 * sum2(add2(na0, nb0)));
        const float n1 = ftanh(xn1 + r1 * sum2(add2(na1, nb1)));
        h0 = n0 + z0 * (h0 - n0);
        h1 = n1 + z1 * (h1 - n1);

        oA[(size_t)t * 2 * HH] = h0;
        oB[(size_t)t * 2 * HH] = h1;
        xr0 = xr0n; xz0 = xz0n; xn0 = xn0n;
        xr1 = xr1n; xz1 = xz1n; xn1 = xn1n;
    }
}

// ---------------------------------------------------------------------------
// Epilogue: single-pass online-softmax attention pooling + sigmoid FC.
// Reads g_out exactly once. One block per batch.
// ---------------------------------------------------------------------------
__global__ void __launch_bounds__(256) attn_fc_kernel(
    const float* __restrict__ attn_w,  // [1,64]
    const float* __restrict__ fc_w,    // [1,64]
    const float* __restrict__ fc_b,    // [1]
    float* __restrict__ y)             // [B,1]
{
    __shared__ float saw[64], sfw[64];
    __shared__ float sm[8], sz[8];
    __shared__ float sctx[8][64];

    const int b    = blockIdx.x;
    const int tid  = threadIdx.x;
    const int warp = tid >> 5;
    const int lane = tid & 31;

    if (tid < 64) {
        saw[tid] = attn_w[tid];
        sfw[tid] = fc_w[tid];
    }
    __syncthreads();

    const float aw0 = saw[lane], aw1 = saw[lane + 32];
    const float* ob = g_out + (size_t)b * TT * 64;

    // online softmax with fused ctx accumulation (per warp over its t's)
    float m = -INFINITY, Z = 0.0f, c0 = 0.0f, c1 = 0.0f;
    for (int t = warp; t < TT; t += 8) {
        const float* p = ob + (size_t)t * 64;
        const float q0 = p[lane];
        const float q1 = p[lane + 32];
        float v = q0 * aw0 + q1 * aw1;
        #pragma unroll
        for (int o = 16; o; o >>= 1) v += __shfl_xor_sync(0xffffffffu, v, o);
        const float mn = fmaxf(m, v);
        const float sc = __expf(m - mn);
        const float e  = __expf(v - mn);
        Z  = Z * sc + e;
        c0 = c0 * sc + e * q0;
        c1 = c1 * sc + e * q1;
        m = mn;
    }
    if (lane == 0) sm[warp] = m;
    __syncthreads();

    float M = sm[0];
    #pragma unroll
    for (int w = 1; w < 8; w++) M = fmaxf(M, sm[w]);
    const float sc = __expf(m - M);
    if (lane == 0) sz[warp] = Z * sc;
    sctx[warp][lane]      = c0 * sc;
    sctx[warp][lane + 32] = c1 * sc;
    __syncthreads();

    if (tid < 32) {
        float Zt = 0.0f, C0 = 0.0f, C1 = 0.0f;
        #pragma unroll
        for (int w = 0; w < 8; w++) {
            Zt += sz[w];
            C0 += sctx[w][lane];
            C1 += sctx[w][lane + 32];
        }
        float v = C0 * sfw[lane] + C1 * sfw[lane + 32];
        #pragma unroll
        for (int o = 16; o; o >>= 1) v += __shfl_xor_sync(0xffffffffu, v, o);
        if (lane == 0) {
            y[b] = frcp(1.0f + __expf(-(__fdividef(v, Zt) + fc_b[0])));
        }
    }
}

extern "C" void kernel_launch(void* const* d_in, const int* in_sizes, int n_in,
                              void* d_out, int out_size) {
    const float* x       = (const float*)d_in[0];
    const float* w_ih_l0 = (const float*)d_in[1];
    const float* w_hh_l0 = (const float*)d_in[2];
    const float* b_ih_l0 = (const float*)d_in[3];
    const float* b_hh_l0 = (const float*)d_in[4];
    const float* w_ih_l1 = (const float*)d_in[5];
    const float* w_hh_l1 = (const float*)d_in[6];
    const float* b_ih_l1 = (const float*)d_in[7];
    const float* b_hh_l1 = (const float*)d_in[8];
    const float* attn_w  = (const float*)d_in[9];
    // d_in[10] = attn_b (cancels in softmax)
    const float* fc_w    = (const float*)d_in[11];
    const float* fc_b    = (const float*)d_in[12];
    float* y = (float*)d_out;

    gru_l0    <<<dim3(BB / 4, 2), 64>>>(x, w_ih_l0, w_hh_l0, b_ih_l0, b_hh_l0);
    gru_l1_xg <<<(BB * 2 * 3) / 4, 128>>>(w_ih_l1, b_ih_l1);
    gru_l1_rec<<<dim3(BB / 4, 2), 64>>>(w_hh_l1, b_hh_l1);
    attn_fc_kernel<<<BB, 256>>>(attn_w, fc_w, fc_b, y);
}

// round 10
// speedup vs baseline: 2.5428x; 1.1049x over previous
#include <cuda_runtime.h>
#include <cuda_fp16.h>
#include <math.h>

#define BB 1024
#define TT 512
#define II 4
#define HH 32
#define GG 96   // 3*H

typedef unsigned long long u64;

// Scratch sequence buffers (allocation-free rule: __device__ globals).
__device__ __half g_h1 [(size_t)BB * TT * 2 * HH];   // layer0 out (fp16) [b][t][dir*32+j]
__device__ __half g_xg [(size_t)2 * BB * TT * GG];   // layer1 input proj (fp16)
__device__ float  g_out[(size_t)BB * TT * 2 * HH];   // layer1 out (fp32)

__device__ __forceinline__ u64 fma2(u64 a, u64 b, u64 c) {
    u64 d;
    asm("fma.rn.f32x2 %0, %1, %2, %3;" : "=l"(d) : "l"(a), "l"(b), "l"(c));
    return d;
}
__device__ __forceinline__ float sum2(u64 v) {
    float lo, hi;
    asm("mov.b64 {%0, %1}, %2;" : "=f"(lo), "=f"(hi) : "l"(v));
    return lo + hi;
}
__device__ __forceinline__ u64 pack2(float lo, float hi) {
    u64 d;
    asm("mov.b64 %0, {%1, %2};" : "=l"(d) : "f"(lo), "f"(hi));
    return d;
}
__device__ __forceinline__ float frcp(float x) {
    float y;
    asm("rcp.approx.f32 %0, %1;" : "=f"(y) : "f"(x));
    return y;
}
__device__ __forceinline__ float fsig(float x) {
    return frcp(1.0f + __expf(-x));
}
__device__ __forceinline__ float ftanh(float x) {
    const float e = __expf(2.0f * x);
    return fmaf(-2.0f, frcp(e + 1.0f), 1.0f);
}
__device__ __forceinline__ __half2 u64_to_h2(u64 v) {
    float lo, hi;
    asm("mov.b64 {%0, %1}, %2;" : "=f"(lo), "=f"(hi) : "l"(v));
    return __floats2half2_rn(lo, hi);
}
__device__ __forceinline__ float h2sum(__half2 v) {
    return __low2float(v) + __high2float(v);
}
#define H2(u) (*(const __half2*)&(u))

// ---------------------------------------------------------------------------
// Layer 0: one warp per (b, dir); lane j owns hidden dim j.
// HFMA2 recurrent MACs: W_hh as 48 half2 regs; h broadcast via fp16 smem slot.
// grid: (B/4, 2), block 128 (4 warps).
// ---------------------------------------------------------------------------
__global__ void __launch_bounds__(128) gru_l0(
    const float* __restrict__ x,      // [B,T,4]
    const float* __restrict__ w_ih,   // [2,96,4]
    const float* __restrict__ w_hh,   // [2,96,32]
    const float* __restrict__ b_ih,   // [2,96]
    const float* __restrict__ b_hh)   // [2,96]
{
    __shared__ __align__(16) __half sh[4][2][32];   // [warp][parity][lane]

    const int warp = threadIdx.x >> 5;
    const int j    = threadIdx.x & 31;
    const int dir  = blockIdx.y;
    const int b    = blockIdx.x * 4 + warp;

    // recurrent weights -> fp16 pairs (16 half2 per gate)
    const u64* w64 = (const u64*)w_hh;
    __half2 wr[16], wz[16], wn[16];
    {
        const int rb = (dir * GG + j) * 16;
        const int zb = (dir * GG + 32 + j) * 16;
        const int nb = (dir * GG + 64 + j) * 16;
        #pragma unroll
        for (int m = 0; m < 16; m++) {
            wr[m] = u64_to_h2(w64[rb + m]);
            wz[m] = u64_to_h2(w64[zb + m]);
            wn[m] = u64_to_h2(w64[nb + m]);
        }
    }
    // input-projection weights fp32 (rows of 4 floats = 2 u64)
    const u64* wi64 = (const u64*)w_ih;
    const u64 wrA = wi64[(dir * GG + j) * 2],      wrB = wi64[(dir * GG + j) * 2 + 1];
    const u64 wzA = wi64[(dir * GG + 32 + j) * 2], wzB = wi64[(dir * GG + 32 + j) * 2 + 1];
    const u64 wnA = wi64[(dir * GG + 64 + j) * 2], wnB = wi64[(dir * GG + 64 + j) * 2 + 1];

    const u64 br2 = pack2(b_ih[dir * GG + j]      + b_hh[dir * GG + j],      0.0f);
    const u64 bz2 = pack2(b_ih[dir * GG + 32 + j] + b_hh[dir * GG + 32 + j], 0.0f);
    const u64 bx2 = pack2(b_ih[dir * GG + 64 + j], 0.0f);
    const float bhn = b_hh[dir * GG + 64 + j];

    float h = 0.0f;
    const int tstep = dir ? -1 : 1;
    int t = dir ? (TT - 1) : 0;

    const ulonglong2* xb2 = (const ulonglong2*)(x + (size_t)b * TT * II);
    __half* ob = g_h1 + (size_t)b * TT * 2 * HH + dir * HH + j;

    ulonglong2 xx = xb2[t];

    for (int s = 0; s < TT; ++s, t += tstep) {
        const int tl = (s == TT - 1) ? t : (t + tstep);
        const ulonglong2 xnx = xb2[tl];

        const int par = s & 1;
        sh[warp][par][j] = __float2half(h);
        __syncwarp();

        // fp32 input projection (tiny)
        const u64 rin2 = fma2(wrA, xx.x, fma2(wrB, xx.y, br2));
        const u64 zin2 = fma2(wzA, xx.x, fma2(wzB, xx.y, bz2));
        const u64 xin2 = fma2(wnA, xx.x, fma2(wnB, xx.y, bx2));

        // fp16 recurrent MACs: 48 HFMA2, 2 chains per gate
        __half2 r0, r1, z0, z1, n0, n1;
        r0 = r1 = z0 = z1 = n0 = n1 = __floats2half2_rn(0.0f, 0.0f);
        const uint4* hv = (const uint4*)sh[warp][par];
        #pragma unroll
        for (int q = 0; q < 4; q++) {
            const uint4 u = hv[q];
            r0 = __hfma2(wr[4 * q],     H2(u.x), r0);
            z0 = __hfma2(wz[4 * q],     H2(u.x), z0);
            n0 = __hfma2(wn[4 * q],     H2(u.x), n0);
            r1 = __hfma2(wr[4 * q + 1], H2(u.y), r1);
            z1 = __hfma2(wz[4 * q + 1], H2(u.y), z1);
            n1 = __hfma2(wn[4 * q + 1], H2(u.y), n1);
            r0 = __hfma2(wr[4 * q + 2], H2(u.z), r0);
            z0 = __hfma2(wz[4 * q + 2], H2(u.z), z0);
            n0 = __hfma2(wn[4 * q + 2], H2(u.z), n0);
            r1 = __hfma2(wr[4 * q + 3], H2(u.w), r1);
            z1 = __hfma2(wz[4 * q + 3], H2(u.w), z1);
            n1 = __hfma2(wn[4 * q + 3], H2(u.w), n1);
        }

        const float r = fsig(sum2(rin2) + h2sum(__hadd2(r0, r1)));
        const float z = fsig(sum2(zin2) + h2sum(__hadd2(z0, z1)));
        const float n = ftanh(sum2(xin2) + r * (bhn + h2sum(__hadd2(n0, n1))));
        h = n + z * (h - n);

        ob[(size_t)t * 2 * HH] = __float2half(h);
        xx = xnx;
    }
}

// ---------------------------------------------------------------------------
// Layer 1 input projection in fp16 HFMA2: xg = h1 @ W_ih^T + b_ih.
// Gate-split warps; 2 timesteps/iter. h1 is already fp16 -> zero conversions.
// block 128, grid 1536.
// ---------------------------------------------------------------------------
__global__ void __launch_bounds__(128) gru_l1_xg(
    const float* __restrict__ w_ih,   // [2,96,64]
    const float* __restrict__ b_ih)   // [2,96]
{
    __shared__ __align__(16) unsigned int sx[4][2][2][32];   // [warp][parity][row][lane-pair]

    const int w = threadIdx.x >> 5;
    const int j = threadIdx.x & 31;

    const int task = blockIdx.x * 4 + w;     // (b*2 + dir)*3 + gate
    const int gate = task % 3;
    const int bd   = task / 3;
    const int dir  = bd & 1;
    const int b    = bd >> 1;

    // lane's weight row: 64 fp32 -> 32 half2 regs
    const u64* w64 = (const u64*)w_ih;
    __half2 wg[32];
    {
        const int rb = (dir * GG + gate * 32 + j) * 32;
        #pragma unroll
        for (int m = 0; m < 32; m++) wg[m] = u64_to_h2(w64[rb + m]);
    }
    const float bias = b_ih[dir * GG + gate * 32 + j];

    const unsigned int* ib = (const unsigned int*)g_h1 + (size_t)b * TT * 32;  // row t: 32 uints (64 halves)
    __half* xo = g_xg + (((size_t)dir * BB + b) * TT) * GG + gate * 32 + j;

    unsigned int a0 = ib[j];        // row 0, halves 2j..2j+1
    unsigned int a1 = ib[32 + j];   // row 1

    for (int s = 0; s < TT / 2; ++s) {
        const int t  = 2 * s;
        const int tn = (s == TT / 2 - 1) ? t : (t + 2);
        const unsigned int p0 = ib[(size_t)tn * 32 + j];
        const unsigned int p1 = ib[(size_t)(tn + 1) * 32 + j];

        const int par = s & 1;
        sx[w][par][0][j] = a0;
        sx[w][par][1][j] = a1;
        __syncwarp();

        __half2 A0, A1, A2, A3, B0, B1, B2, B3;
        A0 = A1 = A2 = A3 = B0 = B1 = B2 = B3 = __floats2half2_rn(0.0f, 0.0f);

        const uint4* r0 = (const uint4*)&sx[w][par][0][0];   // 8 x uint4 = 32 half2
        const uint4* r1 = (const uint4*)&sx[w][par][1][0];
        #pragma unroll
        for (int q = 0; q < 8; q++) {
            const uint4 u = r0[q];
            const uint4 v = r1[q];
            A0 = __hfma2(wg[4 * q],     H2(u.x), A0);
            A1 = __hfma2(wg[4 * q + 1], H2(u.y), A1);
            A2 = __hfma2(wg[4 * q + 2], H2(u.z), A2);
            A3 = __hfma2(wg[4 * q + 3], H2(u.w), A3);
            B0 = __hfma2(wg[4 * q],     H2(v.x), B0);
            B1 = __hfma2(wg[4 * q + 1], H2(v.y), B1);
            B2 = __hfma2(wg[4 * q + 2], H2(v.z), B2);
            B3 = __hfma2(wg[4 * q + 3], H2(v.w), B3);
        }

        const float sA = (h2sum(A0) + h2sum(A1)) + (h2sum(A2) + h2sum(A3));
        const float sB = (h2sum(B0) + h2sum(B1)) + (h2sum(B2) + h2sum(B3));
        xo[(size_t)t * GG]       = __float2half_rn(bias + sA);
        xo[(size_t)(t + 1) * GG] = __float2half_rn(bias + sB);
        a0 = p0; a1 = p1;
    }
}

// ---------------------------------------------------------------------------
// Layer 1 recurrence: one warp per (b, dir), HFMA2 MACs, fp16 xg inputs.
// grid (B/4, 2), block 128.
// ---------------------------------------------------------------------------
__global__ void __launch_bounds__(128) gru_l1_rec(
    const float* __restrict__ w_hh,   // [2,96,32]
    const float* __restrict__ b_hh)   // [2,96]
{
    __shared__ __align__(16) __half sh[4][2][32];

    const int warp = threadIdx.x >> 5;
    const int j    = threadIdx.x & 31;
    const int dir  = blockIdx.y;
    const int b    = blockIdx.x * 4 + warp;

    const u64* w64 = (const u64*)w_hh;
    __half2 wr[16], wz[16], wn[16];
    {
        const int rb = (dir * GG + j) * 16;
        const int zb = (dir * GG + 32 + j) * 16;
        const int nb = (dir * GG + 64 + j) * 16;
        #pragma unroll
        for (int m = 0; m < 16; m++) {
            wr[m] = u64_to_h2(w64[rb + m]);
            wz[m] = u64_to_h2(w64[zb + m]);
            wn[m] = u64_to_h2(w64[nb + m]);
        }
    }
    const float brh = b_hh[dir * GG + j];
    const float bzh = b_hh[dir * GG + 32 + j];
    const float bhn = b_hh[dir * GG + 64 + j];

    float h = 0.0f;
    const int tstep = dir ? -1 : 1;
    int t = dir ? (TT - 1) : 0;

    const __half* xgb = g_xg + (((size_t)dir * BB + b) * TT) * GG;
    float* ob = g_out + (size_t)b * TT * 2 * HH + dir * HH + j;

    float xr = __half2float(xgb[(size_t)t * GG + j]);
    float xz = __half2float(xgb[(size_t)t * GG + 32 + j]);
    float xn = __half2float(xgb[(size_t)t * GG + 64 + j]);

    for (int s = 0; s < TT; ++s, t += tstep) {
        const int tl = (s == TT - 1) ? t : (t + tstep);
        const float xr_n = __half2float(xgb[(size_t)tl * GG + j]);
        const float xz_n = __half2float(xgb[(size_t)tl * GG + 32 + j]);
        const float xn_n = __half2float(xgb[(size_t)tl * GG + 64 + j]);

        const int par = s & 1;
        sh[warp][par][j] = __float2half(h);
        __syncwarp();

        __half2 r0, r1, z0, z1, n0, n1;
        r0 = r1 = z0 = z1 = n0 = n1 = __floats2half2_rn(0.0f, 0.0f);
        const uint4* hv = (const uint4*)sh[warp][par];
        #pragma unroll
        for (int q = 0; q < 4; q++) {
            const uint4 u = hv[q];
            r0 = __hfma2(wr[4 * q],     H2(u.x), r0);
            z0 = __hfma2(wz[4 * q],     H2(u.x), z0);
            n0 = __hfma2(wn[4 * q],     H2(u.x), n0);
            r1 = __hfma2(wr[4 * q + 1], H2(u.y), r1);
            z1 = __hfma2(wz[4 * q + 1], H2(u.y), z1);
            n1 = __hfma2(wn[4 * q + 1], H2(u.y), n1);
            r0 = __hfma2(wr[4 * q + 2], H2(u.z), r0);
            z0 = __hfma2(wz[4 * q + 2], H2(u.z), z0);
            n0 = __hfma2(wn[4 * q + 2], H2(u.z), n0);
            r1 = __hfma2(wr[4 * q + 3], H2(u.w), r1);
            z1 = __hfma2(wz[4 * q + 3], H2(u.w), z1);
            n1 = __hfma2(wn[4 * q + 3], H2(u.w), n1);
        }

        const float r = fsig(xr + brh + h2sum(__hadd2(r0, r1)));
        const float z = fsig(xz + bzh + h2sum(__hadd2(z0, z1)));
        const float n = ftanh(xn + r * (bhn + h2sum(__hadd2(n0, n1))));
        h = n + z * (h - n);

        ob[(size_t)t * 2 * HH] = h;
        xr = xr_n; xz = xz_n; xn = xn_n;
    }
}

// ---------------------------------------------------------------------------
// Epilogue: single-pass online-softmax attention pooling + sigmoid FC.
// ---------------------------------------------------------------------------
__global__ void __launch_bounds__(256) attn_fc_kernel(
    const float* __restrict__ attn_w,  // [1,64]
    const float* __restrict__ fc_w,    // [1,64]
    const float* __restrict__ fc_b,    // [1]
    float* __restrict__ y)             // [B,1]
{
    __shared__ float saw[64], sfw[64];
    __shared__ float sm[8], sz[8];
    __shared__ float sctx[8][64];

    const int b    = blockIdx.x;
    const int tid  = threadIdx.x;
    const int warp = tid >> 5;
    const int lane = tid & 31;

    if (tid < 64) {
        saw[tid] = attn_w[tid];
        sfw[tid] = fc_w[tid];
    }
    __syncthreads();

    const float aw0 = saw[lane], aw1 = saw[lane + 32];
    const float* ob = g_out + (size_t)b * TT * 64;

    float m = -INFINITY, Z = 0.0f, c0 = 0.0f, c1 = 0.0f;
    for (int t = warp; t < TT; t += 8) {
        const float* p = ob + (size_t)t * 64;
        const float q0 = p[lane];
        const float q1 = p[lane + 32];
        float v = q0 * aw0 + q1 * aw1;
        #pragma unroll
        for (int o = 16; o; o >>= 1) v += __shfl_xor_sync(0xffffffffu, v, o);
        const float mn = fmaxf(m, v);
        const float sc = __expf(m - mn);
        const float e  = __expf(v - mn);
        Z  = Z * sc + e;
        c0 = c0 * sc + e * q0;
        c1 = c1 * sc + e * q1;
        m = mn;
    }
    if (lane == 0) sm[warp] = m;
    __syncthreads();

    float M = sm[0];
    #pragma unroll
    for (int w = 1; w < 8; w++) M = fmaxf(M, sm[w]);
    const float sc = __expf(m - M);
    if (lane == 0) sz[warp] = Z * sc;
    sctx[warp][lane]      = c0 * sc;
    sctx[warp][lane + 32] = c1 * sc;
    __syncthreads();

    if (tid < 32) {
        float Zt = 0.0f, C0 = 0.0f, C1 = 0.0f;
        #pragma unroll
        for (int w = 0; w < 8; w++) {
            Zt += sz[w];
            C0 += sctx[w][lane];
            C1 += sctx[w][lane + 32];
        }
        float v = C0 * sfw[lane] + C1 * sfw[lane + 32];
        #pragma unroll
        for (int o = 16; o; o >>= 1) v += __shfl_xor_sync(0xffffffffu, v, o);
        if (lane == 0) {
            y[b] = frcp(1.0f + __expf(-(__fdividef(v, Zt) + fc_b[0])));
        }
    }
}

extern "C" void kernel_launch(void* const* d_in, const int* in_sizes, int n_in,
                              void* d_out, int out_size) {
    const float* x       = (const float*)d_in[0];
    const float* w_ih_l0 = (const float*)d_in[1];
    const float* w_hh_l0 = (const float*)d_in[2];
    const float* b_ih_l0 = (const float*)d_in[3];
    const float* b_hh_l0 = (const float*)d_in[4];
    const float* w_ih_l1 = (const float*)d_in[5];
    const float* w_hh_l1 = (const float*)d_in[6];
    const float* b_ih_l1 = (const float*)d_in[7];
    const float* b_hh_l1 = (const float*)d_in[8];
    const float* attn_w  = (const float*)d_in[9];
    // d_in[10] = attn_b (cancels in softmax)
    const float* fc_w    = (const float*)d_in[11];
    const float* fc_b    = (const float*)d_in[12];
    float* y = (float*)d_out;

    gru_l0    <<<dim3(BB / 4, 2), 128>>>(x, w_ih_l0, w_hh_l0, b_ih_l0, b_hh_l0);
    gru_l1_xg <<<(BB * 2 * 3) / 4, 128>>>(w_ih_l1, b_ih_l1);
    gru_l1_rec<<<dim3(BB / 4, 2), 128>>>(w_hh_l1, b_hh_l1);
    attn_fc_kernel<<<BB, 256>>>(attn_w, fc_w, fc_b, y);
}

// round 11
// speedup vs baseline: 2.9183x; 1.1477x over previous
#include <cuda_runtime.h>
#include <cuda_fp16.h>
#include <math.h>

#define BB 1024
#define TT 512
#define II 4
#define HH 32
#define GG 96   // 3*H

typedef unsigned long long u64;

// Scratch sequence buffers (allocation-free rule: __device__ globals).
__device__ __half g_h1 [(size_t)BB * TT * 2 * HH];   // layer0 out (fp16) [b][t][dir*32+j]
__device__ u64    g_xg [(size_t)2 * BB * TT * HH];   // layer1 gates packed (r,z,n,pad) halves per (t,j)
__device__ float  g_out[(size_t)BB * TT * 2 * HH];   // layer1 out (fp32)

__device__ __forceinline__ u64 fma2(u64 a, u64 b, u64 c) {
    u64 d;
    asm("fma.rn.f32x2 %0, %1, %2, %3;" : "=l"(d) : "l"(a), "l"(b), "l"(c));
    return d;
}
__device__ __forceinline__ float sum2(u64 v) {
    float lo, hi;
    asm("mov.b64 {%0, %1}, %2;" : "=f"(lo), "=f"(hi) : "l"(v));
    return lo + hi;
}
__device__ __forceinline__ u64 pack2(float lo, float hi) {
    u64 d;
    asm("mov.b64 %0, {%1, %2};" : "=l"(d) : "f"(lo), "f"(hi));
    return d;
}
__device__ __forceinline__ float frcp(float x) {
    float y;
    asm("rcp.approx.f32 %0, %1;" : "=f"(y) : "f"(x));
    return y;
}
__device__ __forceinline__ float fsig(float x) {
    return frcp(1.0f + __expf(-x));
}
__device__ __forceinline__ float ftanh(float x) {
    const float e = __expf(2.0f * x);
    return fmaf(-2.0f, frcp(e + 1.0f), 1.0f);
}
__device__ __forceinline__ __half2 u64_to_h2(u64 v) {
    float lo, hi;
    asm("mov.b64 {%0, %1}, %2;" : "=f"(lo), "=f"(hi) : "l"(v));
    return __floats2half2_rn(lo, hi);
}
__device__ __forceinline__ float h2sum(__half2 v) {
    return __low2float(v) + __high2float(v);
}
#define H2(u) (*(const __half2*)&(u))

// ---------------------------------------------------------------------------
// Layer 0: one warp per (b, dir); lane j owns hidden dim j. HFMA2 MACs.
// Prefetch depth 2 on x. grid: (B/4, 2), block 128.
// ---------------------------------------------------------------------------
__global__ void __launch_bounds__(128) gru_l0(
    const float* __restrict__ x,      // [B,T,4]
    const float* __restrict__ w_ih,   // [2,96,4]
    const float* __restrict__ w_hh,   // [2,96,32]
    const float* __restrict__ b_ih,   // [2,96]
    const float* __restrict__ b_hh)   // [2,96]
{
    __shared__ __align__(16) __half sh[4][2][32];   // [warp][parity][lane]

    const int warp = threadIdx.x >> 5;
    const int j    = threadIdx.x & 31;
    const int dir  = blockIdx.y;
    const int b    = blockIdx.x * 4 + warp;

    const u64* w64 = (const u64*)w_hh;
    __half2 wr[16], wz[16], wn[16];
    {
        const int rb = (dir * GG + j) * 16;
        const int zb = (dir * GG + 32 + j) * 16;
        const int nb = (dir * GG + 64 + j) * 16;
        #pragma unroll
        for (int m = 0; m < 16; m++) {
            wr[m] = u64_to_h2(w64[rb + m]);
            wz[m] = u64_to_h2(w64[zb + m]);
            wn[m] = u64_to_h2(w64[nb + m]);
        }
    }
    const u64* wi64 = (const u64*)w_ih;
    const u64 wrA = wi64[(dir * GG + j) * 2],      wrB = wi64[(dir * GG + j) * 2 + 1];
    const u64 wzA = wi64[(dir * GG + 32 + j) * 2], wzB = wi64[(dir * GG + 32 + j) * 2 + 1];
    const u64 wnA = wi64[(dir * GG + 64 + j) * 2], wnB = wi64[(dir * GG + 64 + j) * 2 + 1];

    const u64 br2 = pack2(b_ih[dir * GG + j]      + b_hh[dir * GG + j],      0.0f);
    const u64 bz2 = pack2(b_ih[dir * GG + 32 + j] + b_hh[dir * GG + 32 + j], 0.0f);
    const u64 bx2 = pack2(b_ih[dir * GG + 64 + j], 0.0f);
    const float bhn = b_hh[dir * GG + 64 + j];

    float h = 0.0f;
    const int tstep = dir ? -1 : 1;
    int t = dir ? (TT - 1) : 0;

    const ulonglong2* xb2 = (const ulonglong2*)(x + (size_t)b * TT * II);
    __half* ob = g_h1 + (size_t)b * TT * 2 * HH + dir * HH + j;

    // prefetch queue depth 2
    ulonglong2 xq0 = xb2[t];
    ulonglong2 xq1 = xb2[t + tstep * (TT > 1 ? 1 : 0)];

    for (int s = 0; s < TT; ++s, t += tstep) {
        int tp = t + 2 * tstep;
        tp = (tp < 0) ? 0 : ((tp >= TT) ? (TT - 1) : tp);
        const ulonglong2 xq2 = xb2[tp];

        const int par = s & 1;
        sh[warp][par][j] = __float2half(h);
        __syncwarp();

        const u64 rin2 = fma2(wrA, xq0.x, fma2(wrB, xq0.y, br2));
        const u64 zin2 = fma2(wzA, xq0.x, fma2(wzB, xq0.y, bz2));
        const u64 xin2 = fma2(wnA, xq0.x, fma2(wnB, xq0.y, bx2));

        __half2 r0, r1, z0, z1, n0, n1;
        r0 = r1 = z0 = z1 = n0 = n1 = __floats2half2_rn(0.0f, 0.0f);
        const uint4* hv = (const uint4*)sh[warp][par];
        #pragma unroll
        for (int q = 0; q < 4; q++) {
            const uint4 u = hv[q];
            r0 = __hfma2(wr[4 * q],     H2(u.x), r0);
            z0 = __hfma2(wz[4 * q],     H2(u.x), z0);
            n0 = __hfma2(wn[4 * q],     H2(u.x), n0);
            r1 = __hfma2(wr[4 * q + 1], H2(u.y), r1);
            z1 = __hfma2(wz[4 * q + 1], H2(u.y), z1);
            n1 = __hfma2(wn[4 * q + 1], H2(u.y), n1);
            r0 = __hfma2(wr[4 * q + 2], H2(u.z), r0);
            z0 = __hfma2(wz[4 * q + 2], H2(u.z), z0);
            n0 = __hfma2(wn[4 * q + 2], H2(u.z), n0);
            r1 = __hfma2(wr[4 * q + 3], H2(u.w), r1);
            z1 = __hfma2(wz[4 * q + 3], H2(u.w), z1);
            n1 = __hfma2(wn[4 * q + 3], H2(u.w), n1);
        }

        const float r = fsig(sum2(rin2) + h2sum(__hadd2(r0, r1)));
        const float z = fsig(sum2(zin2) + h2sum(__hadd2(z0, z1)));
        const float n = ftanh(sum2(xin2) + r * (bhn + h2sum(__hadd2(n0, n1))));
        h = n + z * (h - n);

        ob[(size_t)t * 2 * HH] = __float2half(h);
        xq0 = xq1; xq1 = xq2;
    }
}

// ---------------------------------------------------------------------------
// Layer 1 input projection (all 3 gates per warp), packed u64 output:
// g_xg[((dir*B+b)*T + t)*32 + j] = halves (r, z, n, 0).
// One warp per (b, dir, half-of-T). block 128, grid 1024.
// ---------------------------------------------------------------------------
__global__ void __launch_bounds__(128) gru_l1_xg(
    const float* __restrict__ w_ih,   // [2,96,64]
    const float* __restrict__ b_ih)   // [2,96]
{
    __shared__ __align__(16) unsigned int sx[4][2][2][32];  // [warp][parity][row][lane]

    const int w = threadIdx.x >> 5;
    const int j = threadIdx.x & 31;

    const int task  = blockIdx.x * 4 + w;   // (b*2 + dir)*2 + chunk
    const int chunk = task & 1;
    const int bd    = task >> 1;
    const int dir   = bd & 1;
    const int b     = bd >> 1;

    // weights: 3 gate rows of 64 fp32 -> 3 x 32 half2 regs
    const u64* w64 = (const u64*)w_ih;
    __half2 wgr[32], wgz[32], wgn[32];
    {
        const int rb = (dir * GG + j) * 32;
        const int zb = (dir * GG + 32 + j) * 32;
        const int nb = (dir * GG + 64 + j) * 32;
        #pragma unroll
        for (int m = 0; m < 32; m++) {
            wgr[m] = u64_to_h2(w64[rb + m]);
            wgz[m] = u64_to_h2(w64[zb + m]);
            wgn[m] = u64_to_h2(w64[nb + m]);
        }
    }
    const float br = b_ih[dir * GG + j];
    const float bz = b_ih[dir * GG + 32 + j];
    const float bn = b_ih[dir * GG + 64 + j];

    const unsigned int* ib = (const unsigned int*)g_h1 + (size_t)b * TT * 32;
    u64* xo = g_xg + ((size_t)(dir * BB + b) * TT) * 32 + j;

    const int t0 = chunk * (TT / 2);
    unsigned int a0 = ib[(size_t)t0 * 32 + j];
    unsigned int a1 = ib[(size_t)(t0 + 1) * 32 + j];

    for (int s = 0; s < TT / 4; ++s) {
        const int t  = t0 + 2 * s;
        const int tn = (s == TT / 4 - 1) ? t : (t + 2);
        const unsigned int p0 = ib[(size_t)tn * 32 + j];
        const unsigned int p1 = ib[(size_t)(tn + 1) * 32 + j];

        const int par = s & 1;
        sx[w][par][0][j] = a0;
        sx[w][par][1][j] = a1;
        __syncwarp();

        __half2 R0, R1, Z0, Z1, N0, N1;       // row 0
        __half2 R2, R3, Z2, Z3, N2, N3;       // row 1
        R0 = R1 = Z0 = Z1 = N0 = N1 = __floats2half2_rn(0.0f, 0.0f);
        R2 = R3 = Z2 = Z3 = N2 = N3 = __floats2half2_rn(0.0f, 0.0f);

        const uint4* r0p = (const uint4*)&sx[w][par][0][0];
        const uint4* r1p = (const uint4*)&sx[w][par][1][0];
        #pragma unroll
        for (int q = 0; q < 8; q++) {
            const uint4 u = r0p[q];
            const uint4 v = r1p[q];
            R0 = __hfma2(wgr[4 * q],     H2(u.x), R0);
            Z0 = __hfma2(wgz[4 * q],     H2(u.x), Z0);
            N0 = __hfma2(wgn[4 * q],     H2(u.x), N0);
            R1 = __hfma2(wgr[4 * q + 1], H2(u.y), R1);
            Z1 = __hfma2(wgz[4 * q + 1], H2(u.y), Z1);
            N1 = __hfma2(wgn[4 * q + 1], H2(u.y), N1);
            R0 = __hfma2(wgr[4 * q + 2], H2(u.z), R0);
            Z0 = __hfma2(wgz[4 * q + 2], H2(u.z), Z0);
            N0 = __hfma2(wgn[4 * q + 2], H2(u.z), N0);
            R1 = __hfma2(wgr[4 * q + 3], H2(u.w), R1);
            Z1 = __hfma2(wgz[4 * q + 3], H2(u.w), Z1);
            N1 = __hfma2(wgn[4 * q + 3], H2(u.w), N1);

            R2 = __hfma2(wgr[4 * q],     H2(v.x), R2);
            Z2 = __hfma2(wgz[4 * q],     H2(v.x), Z2);
            N2 = __hfma2(wgn[4 * q],     H2(v.x), N2);
            R3 = __hfma2(wgr[4 * q + 1], H2(v.y), R3);
            Z3 = __hfma2(wgz[4 * q + 1], H2(v.y), Z3);
            N3 = __hfma2(wgn[4 * q + 1], H2(v.y), N3);
            R2 = __hfma2(wgr[4 * q + 2], H2(v.z), R2);
            Z2 = __hfma2(wgz[4 * q + 2], H2(v.z), Z2);
            N2 = __hfma2(wgn[4 * q + 2], H2(v.z), N2);
            R3 = __hfma2(wgr[4 * q + 3], H2(v.w), R3);
            Z3 = __hfma2(wgz[4 * q + 3], H2(v.w), Z3);
            N3 = __hfma2(wgn[4 * q + 3], H2(v.w), N3);
        }

        // row 0 pack: (r,z) , (n,0)
        {
            const float rv = br + h2sum(__hadd2(R0, R1));
            const float zv = bz + h2sum(__hadd2(Z0, Z1));
            const float nv = bn + h2sum(__hadd2(N0, N1));
            const __half2 lo = __floats2half2_rn(rv, zv);
            const __half2 hi = __floats2half2_rn(nv, 0.0f);
            u64 pk;
            asm("mov.b64 %0, {%1, %2};" : "=l"(pk)
                : "r"(*(const unsigned int*)&lo), "r"(*(const unsigned int*)&hi));
            xo[(size_t)t * 32] = pk;
        }
        // row 1
        {
            const float rv = br + h2sum(__hadd2(R2, R3));
            const float zv = bz + h2sum(__hadd2(Z2, Z3));
            const float nv = bn + h2sum(__hadd2(N2, N3));
            const __half2 lo = __floats2half2_rn(rv, zv);
            const __half2 hi = __floats2half2_rn(nv, 0.0f);
            u64 pk;
            asm("mov.b64 %0, {%1, %2};" : "=l"(pk)
                : "r"(*(const unsigned int*)&lo), "r"(*(const unsigned int*)&hi));
            xo[(size_t)(t + 1) * 32] = pk;
        }
        a0 = p0; a1 = p1;
    }
}

// ---------------------------------------------------------------------------
// Layer 1 recurrence: one warp per (b, dir); single u64 gate load per step,
// prefetch queue depth 3. grid (B/4, 2), block 128.
// ---------------------------------------------------------------------------
__global__ void __launch_bounds__(128) gru_l1_rec(
    const float* __restrict__ w_hh,   // [2,96,32]
    const float* __restrict__ b_hh)   // [2,96]
{
    __shared__ __align__(16) __half sh[4][2][32];

    const int warp = threadIdx.x >> 5;
    const int j    = threadIdx.x & 31;
    const int dir  = blockIdx.y;
    const int b    = blockIdx.x * 4 + warp;

    const u64* w64 = (const u64*)w_hh;
    __half2 wr[16], wz[16], wn[16];
    {
        const int rb = (dir * GG + j) * 16;
        const int zb = (dir * GG + 32 + j) * 16;
        const int nb = (dir * GG + 64 + j) * 16;
        #pragma unroll
        for (int m = 0; m < 16; m++) {
            wr[m] = u64_to_h2(w64[rb + m]);
            wz[m] = u64_to_h2(w64[zb + m]);
            wn[m] = u64_to_h2(w64[nb + m]);
        }
    }
    const float brh = b_hh[dir * GG + j];
    const float bzh = b_hh[dir * GG + 32 + j];
    const float bhn = b_hh[dir * GG + 64 + j];

    float h = 0.0f;
    const int tstep = dir ? -1 : 1;
    int t = dir ? (TT - 1) : 0;

    const u64* xgb = g_xg + ((size_t)(dir * BB + b) * TT) * 32 + j;
    float* ob = g_out + (size_t)b * TT * 2 * HH + dir * HH + j;

    // prefetch queue depth 3
    u64 q0 = xgb[(size_t)t * 32];
    u64 q1 = xgb[(size_t)(t + tstep) * 32];
    u64 q2 = xgb[(size_t)(t + 2 * tstep) * 32];

    for (int s = 0; s < TT; ++s, t += tstep) {
        int tp = t + 3 * tstep;
        tp = (tp < 0) ? 0 : ((tp >= TT) ? (TT - 1) : tp);
        const u64 q3 = xgb[(size_t)tp * 32];

        const int par = s & 1;
        sh[warp][par][j] = __float2half(h);
        __syncwarp();

        // unpack gate inputs for this step
        unsigned int lo_u, hi_u;
        asm("mov.b64 {%0, %1}, %2;" : "=r"(lo_u), "=r"(hi_u) : "l"(q0));
        const __half2 lo = H2(lo_u);
        const __half2 hi = H2(hi_u);
        const float xr = __low2float(lo);
        const float xz = __high2float(lo);
        const float xn = __low2float(hi);

        __half2 r0, r1, z0, z1, n0, n1;
        r0 = r1 = z0 = z1 = n0 = n1 = __floats2half2_rn(0.0f, 0.0f);
        const uint4* hv = (const uint4*)sh[warp][par];
        #pragma unroll
        for (int q = 0; q < 4; q++) {
            const uint4 u = hv[q];
            r0 = __hfma2(wr[4 * q],     H2(u.x), r0);
            z0 = __hfma2(wz[4 * q],     H2(u.x), z0);
            n0 = __hfma2(wn[4 * q],     H2(u.x), n0);
            r1 = __hfma2(wr[4 * q + 1], H2(u.y), r1);
            z1 = __hfma2(wz[4 * q + 1], H2(u.y), z1);
            n1 = __hfma2(wn[4 * q + 1], H2(u.y), n1);
            r0 = __hfma2(wr[4 * q + 2], H2(u.z), r0);
            z0 = __hfma2(wz[4 * q + 2], H2(u.z), z0);
            n0 = __hfma2(wn[4 * q + 2], H2(u.z), n0);
            r1 = __hfma2(wr[4 * q + 3], H2(u.w), r1);
            z1 = __hfma2(wz[4 * q + 3], H2(u.w), z1);
            n1 = __hfma2(wn[4 * q + 3], H2(u.w), n1);
        }

        const float r = fsig(xr + brh + h2sum(__hadd2(r0, r1)));
        const float z = fsig(xz + bzh + h2sum(__hadd2(z0, z1)));
        const float n = ftanh(xn + r * (bhn + h2sum(__hadd2(n0, n1))));
        h = n + z * (h - n);

        ob[(size_t)t * 2 * HH] = h;
        q0 = q1; q1 = q2; q2 = q3;
    }
}

// ---------------------------------------------------------------------------
// Epilogue: single-pass online-softmax attention pooling + sigmoid FC.
// ---------------------------------------------------------------------------
__global__ void __launch_bounds__(256) attn_fc_kernel(
    const float* __restrict__ attn_w,  // [1,64]
    const float* __restrict__ fc_w,    // [1,64]
    const float* __restrict__ fc_b,    // [1]
    float* __restrict__ y)             // [B,1]
{
    __shared__ float saw[64], sfw[64];
    __shared__ float sm[8], sz[8];
    __shared__ float sctx[8][64];

    const int b    = blockIdx.x;
    const int tid  = threadIdx.x;
    const int warp = tid >> 5;
    const int lane = tid & 31;

    if (tid < 64) {
        saw[tid] = attn_w[tid];
        sfw[tid] = fc_w[tid];
    }
    __syncthreads();

    const float aw0 = saw[lane], aw1 = saw[lane + 32];
    const float* ob = g_out + (size_t)b * TT * 64;

    float m = -INFINITY, Z = 0.0f, c0 = 0.0f, c1 = 0.0f;
    for (int t = warp; t < TT; t += 8) {
        const float* p = ob + (size_t)t * 64;
        const float q0 = p[lane];
        const float q1 = p[lane + 32];
        float v = q0 * aw0 + q1 * aw1;
        #pragma unroll
        for (int o = 16; o; o >>= 1) v += __shfl_xor_sync(0xffffffffu, v, o);
        const float mn = fmaxf(m, v);
        const float sc = __expf(m - mn);
        const float e  = __expf(v - mn);
        Z  = Z * sc + e;
        c0 = c0 * sc + e * q0;
        c1 = c1 * sc + e * q1;
        m = mn;
    }
    if (lane == 0) sm[warp] = m;
    __syncthreads();

    float M = sm[0];
    #pragma unroll
    for (int w = 1; w < 8; w++) M = fmaxf(M, sm[w]);
    const float sc = __expf(m - M);
    if (lane == 0) sz[warp] = Z * sc;
    sctx[warp][lane]      = c0 * sc;
    sctx[warp][lane + 32] = c1 * sc;
    __syncthreads();

    if (tid < 32) {
        float Zt = 0.0f, C0 = 0.0f, C1 = 0.0f;
        #pragma unroll
        for (int w = 0; w < 8; w++) {
            Zt += sz[w];
            C0 += sctx[w][lane];
            C1 += sctx[w][lane + 32];
        }
        float v = C0 * sfw[lane] + C1 * sfw[lane + 32];
        #pragma unroll
        for (int o = 16; o; o >>= 1) v += __shfl_xor_sync(0xffffffffu, v, o);
        if (lane == 0) {
            y[b] = frcp(1.0f + __expf(-(__fdividef(v, Zt) + fc_b[0])));
        }
    }
}

extern "C" void kernel_launch(void* const* d_in, const int* in_sizes, int n_in,
                              void* d_out, int out_size) {
    const float* x       = (const float*)d_in[0];
    const float* w_ih_l0 = (const float*)d_in[1];
    const float* w_hh_l0 = (const float*)d_in[2];
    const float* b_ih_l0 = (const float*)d_in[3];
    const float* b_hh_l0 = (const float*)d_in[4];
    const float* w_ih_l1 = (const float*)d_in[5];
    const float* w_hh_l1 = (const float*)d_in[6];
    const float* b_ih_l1 = (const float*)d_in[7];
    const float* b_hh_l1 = (const float*)d_in[8];
    const float* attn_w  = (const float*)d_in[9];
    // d_in[10] = attn_b (cancels in softmax)
    const float* fc_w    = (const float*)d_in[11];
    const float* fc_b    = (const float*)d_in[12];
    float* y = (float*)d_out;

    gru_l0    <<<dim3(BB / 4, 2), 128>>>(x, w_ih_l0, w_hh_l0, b_ih_l0, b_hh_l0);
    gru_l1_xg <<<(BB * 2 * 2) / 4, 128>>>(w_ih_l1, b_ih_l1);
    gru_l1_rec<<<dim3(BB / 4, 2), 128>>>(w_hh_l1, b_hh_l1);
    attn_fc_kernel<<<BB, 256>>>(attn_w, fc_w, fc_b, y);
}